// round 9
// baseline (speedup 1.0000x reference)
#include <cuda_runtime.h>
#include <cuda_bf16.h>
#include <cstdint>

// Problem constants
#define BATCH 4
#define SEQ   1024
#define CDIM  2048
#define NHEAD 32
#define HDIM  64
#define QKVN  (3*CDIM)          // 6144
#define MROWS (BATCH*SEQ)       // 4096

// Scratch (device globals: allocation-free rule)
__device__ float g_qkv[(size_t)MROWS * QKVN];
__device__ float g_q[(size_t)BATCH*NHEAD*SEQ*HDIM];
__device__ float g_k[(size_t)BATCH*NHEAD*SEQ*HDIM];
__device__ float g_v[(size_t)BATCH*NHEAD*SEQ*HDIM];
// tf32-pre-rounded operand copies
__device__ float g_xc[(size_t)MROWS * CDIM];
__device__ float g_w1[(size_t)QKVN * CDIM];
__device__ float g_w2[(size_t)CDIM * CDIM];

// ---------------------------------------------------------------------------
// helpers
// ---------------------------------------------------------------------------
__device__ __forceinline__ uint32_t smem_u32(const void* p) {
    uint32_t a;
    asm("{ .reg .u64 t; cvta.to.shared.u64 t, %1; cvt.u32.u64 %0, t; }" : "=r"(a) : "l"(p));
    return a;
}
#define CP16(dst, src) \
    asm volatile("cp.async.cg.shared.global [%0], [%1], 16;" :: "r"(dst), "l"(src) : "memory")
#define CP_COMMIT() asm volatile("cp.async.commit_group;" ::: "memory")
#define CP_WAIT1()  asm volatile("cp.async.wait_group 1;" ::: "memory")
#define CP_WAIT0()  asm volatile("cp.async.wait_group 0;" ::: "memory")

__device__ __forceinline__ void ldsm_x4(uint32_t a[4], uint32_t addr) {
    asm volatile("ldmatrix.sync.aligned.m8n8.x4.shared.b16 {%0,%1,%2,%3}, [%4];"
        : "=r"(a[0]), "=r"(a[1]), "=r"(a[2]), "=r"(a[3]) : "r"(addr));
}
__device__ __forceinline__ void ldsm_x2(uint32_t a[2], uint32_t addr) {
    asm volatile("ldmatrix.sync.aligned.m8n8.x2.shared.b16 {%0,%1}, [%2];"
        : "=r"(a[0]), "=r"(a[1]) : "r"(addr));
}
__device__ __forceinline__ float cvt_tf32_f(float x) {
    uint32_t r;
    asm("cvt.rna.tf32.f32 %0, %1;" : "=r"(r) : "f"(x));
    return __uint_as_float(r);
}
__device__ __forceinline__ void mma_tf32(float c[4], const uint32_t a[4], const uint32_t b[2]) {
    asm volatile(
        "mma.sync.aligned.m16n8k8.row.col.f32.tf32.tf32.f32 "
        "{%0,%1,%2,%3}, {%4,%5,%6,%7}, {%8,%9}, {%0,%1,%2,%3};"
        : "+f"(c[0]), "+f"(c[1]), "+f"(c[2]), "+f"(c[3])
        : "r"(a[0]), "r"(a[1]), "r"(a[2]), "r"(a[3]), "r"(b[0]), "r"(b[1]));
}

// ---------------------------------------------------------------------------
// tf32 pre-round pass: out[i] = rna_tf32(in[i])  (idempotent)
// ---------------------------------------------------------------------------
__global__ void __launch_bounds__(256) cvt_tf32_copy(
    const float* __restrict__ in, float* __restrict__ out, int n4)
{
    int i = blockIdx.x * 256 + threadIdx.x;
    if (i < n4) {
        float4 v = reinterpret_cast<const float4*>(in)[i];
        v.x = cvt_tf32_f(v.x); v.y = cvt_tf32_f(v.y);
        v.z = cvt_tf32_f(v.z); v.w = cvt_tf32_f(v.w);
        reinterpret_cast<float4*>(out)[i] = v;
    }
}

// ---------------------------------------------------------------------------
// TF32 mma.sync GEMM: C[M,N] = A[M,K] @ B[N,K]^T + bias[N]
// CTA tile 128x256, warp tile 64x64 (8 warps 2x4), BK=32, 3-stage cp.async.
// Operands pre-rounded to tf32. Raises MMA:smem-traffic ratio ~1.45x vs the
// 128x128 tile so the tensor pipe (not the smem crossbar) binds.
// ---------------------------------------------------------------------------
#define BKC 32
#define BN2 256
#define STAGE_BYTES2 49152            // A 16KB + B 32KB
#define GEMM_SMEM (3 * STAGE_BYTES2)  // 147456

__global__ void __launch_bounds__(256, 1) gemm_tf32(
    const float* __restrict__ A, const float* __restrict__ B,
    const float* __restrict__ bias, float* __restrict__ C,
    int M, int N, int K)
{
    extern __shared__ char smem[];
    const uint32_t sb = smem_u32(smem);
    const int tid  = threadIdx.x;
    const int lane = tid & 31;
    const int wid  = tid >> 5;
    const int row0 = blockIdx.y * 128;
    const int col0 = blockIdx.x * BN2;
    const int wm = (wid >> 2) * 64;        // 2 m-bands
    const int wn = (wid & 3) * 64;         // 4 n-bands

    // cp.async staging: thread covers rows r+32l; A l<4, B l<8
    const int r = tid >> 3;
    const int c = tid & 7;
    const float* aSrc = A + (size_t)(row0 + r) * K + c * 4;
    const float* bSrc = B + (size_t)(col0 + r) * K + c * 4;
    uint32_t dOff[8];
    #pragma unroll
    for (int l = 0; l < 8; l++) {
        int row = r + 32 * l;
        dOff[l] = (uint32_t)(row * 128 + ((c * 16) ^ ((row & 7) << 4)));
    }

    const int nk = K / BKC;

    uint32_t aRow[4], bRow[8];
    #pragma unroll
    for (int mi = 0; mi < 4; mi++) aRow[mi] = (uint32_t)((wm + mi * 16 + (lane & 15)) * 128);
    #pragma unroll
    for (int ni = 0; ni < 8; ni++) bRow[ni] = (uint32_t)((wn + ni * 8 + (lane & 7)) * 128);
    const uint32_t xorv = (uint32_t)((lane & 7) << 4);
    const uint32_t aseg = (uint32_t)((lane >> 4) * 16);
    const uint32_t bseg = (uint32_t)(((lane >> 3) & 1) * 16);

    float acc[32][4];
    #pragma unroll
    for (int t = 0; t < 32; t++)
        #pragma unroll
        for (int j = 0; j < 4; j++) acc[t][j] = 0.f;

    // prologue: stages 0,1
    #pragma unroll
    for (int p = 0; p < 2; p++) {
        uint32_t base = sb + p * STAGE_BYTES2;
        size_t koff = (size_t)p * BKC;
        #pragma unroll
        for (int l = 0; l < 4; l++) CP16(base + dOff[l],         aSrc + (size_t)l * 32 * K + koff);
        #pragma unroll
        for (int l = 0; l < 8; l++) CP16(base + 16384 + dOff[l], bSrc + (size_t)l * 32 * K + koff);
        CP_COMMIT();
    }

    int sCur = 0, sNext = 2;
    for (int i = 0; i < nk; i++) {
        CP_WAIT1();
        __syncthreads();

        if (i + 2 < nk) {
            uint32_t base = sb + sNext * STAGE_BYTES2;
            size_t koff = (size_t)(i + 2) * BKC;
            #pragma unroll
            for (int l = 0; l < 4; l++) CP16(base + dOff[l],         aSrc + (size_t)l * 32 * K + koff);
            #pragma unroll
            for (int l = 0; l < 8; l++) CP16(base + 16384 + dOff[l], bSrc + (size_t)l * 32 * K + koff);
        }
        CP_COMMIT();

        const uint32_t aBase = sb + sCur * STAGE_BYTES2;
        const uint32_t bBase = aBase + 16384;

        #pragma unroll
        for (int ks = 0; ks < 4; ks++) {
            const uint32_t kb = (uint32_t)(ks * 32);
            uint32_t af[4][4], bf[8][2];
            #pragma unroll
            for (int mi = 0; mi < 4; mi++)
                ldsm_x4(af[mi], aBase + aRow[mi] + ((kb + aseg) ^ xorv));
            #pragma unroll
            for (int ni = 0; ni < 8; ni++)
                ldsm_x2(bf[ni], bBase + bRow[ni] + ((kb + bseg) ^ xorv));
            #pragma unroll
            for (int mi = 0; mi < 4; mi++)
                #pragma unroll
                for (int ni = 0; ni < 8; ni++)
                    mma_tf32(acc[mi * 8 + ni], af[mi], bf[ni]);
        }

        sCur = (sCur + 1) % 3;
        sNext = (sNext + 1) % 3;
    }

    const int gq = lane >> 2;
    const int qc = lane & 3;
    #pragma unroll
    for (int mi = 0; mi < 4; mi++) {
        #pragma unroll
        for (int ni = 0; ni < 8; ni++) {
            const float* ac = acc[mi * 8 + ni];
            int colb = col0 + wn + ni * 8 + qc * 2;
            float b0 = __ldg(&bias[colb]);
            float b1 = __ldg(&bias[colb + 1]);
            size_t base0 = (size_t)(row0 + wm + mi * 16 + gq) * N + colb;
            C[base0]         = ac[0] + b0;
            C[base0 + 1]     = ac[1] + b1;
            C[base0 + 8 * (size_t)N]     = ac[2] + b0;
            C[base0 + 8 * (size_t)N + 1] = ac[3] + b1;
        }
    }
}

// ---------------------------------------------------------------------------
// RoPE + transpose; q/k/v stored tf32-RNA-rounded (feed tensor-core attn)
// ---------------------------------------------------------------------------
__global__ void __launch_bounds__(256) rope_transpose(
    const float* __restrict__ qkv, const float* __restrict__ rope,
    float* __restrict__ q, float* __restrict__ k, float* __restrict__ v)
{
    int idx = blockIdx.x * 256 + threadIdx.x;
    int d = idx & 63;
    int h = (idx >> 6) & 31;
    int t = (idx >> 11) & 1023;
    int b = idx >> 21;

    const float* row = qkv + (size_t)(b * SEQ + t) * QKVN;
    int col = h * HDIM + d;

    float qv, kv;
    if (d < 32) {
        int j = d & 15;
        float cs = rope[(t * 16 + j) * 2 + 0];
        float sn = rope[(t * 16 + j) * 2 + 1];
        if (d < 16) {
            qv = row[col]        * cs - row[col + 16]        * sn;
            kv = row[CDIM + col] * cs - row[CDIM + col + 16] * sn;
        } else {
            qv = row[col]        * cs + row[col - 16]        * sn;
            kv = row[CDIM + col] * cs + row[CDIM + col - 16] * sn;
        }
    } else {
        qv = row[col];
        kv = row[CDIM + col];
    }
    float vv = row[2 * CDIM + col];

    size_t o = ((size_t)(b * NHEAD + h) * SEQ + t) * HDIM + d;
    q[o] = cvt_tf32_f(qv); k[o] = cvt_tf32_f(kv); v[o] = cvt_tf32_f(vv);
}

// ---------------------------------------------------------------------------
// Tensor-core causal flash attention (tf32 mma.sync). Unchanged from R8.
// ---------------------------------------------------------------------------
#define ATTN_SMEM2 98304
#define OFF_QS 0u
#define OFF_KS 32768u
#define OFF_VT 49152u
#define OFF_PS 65536u

__global__ void __launch_bounds__(256) attn_tc(
    const float* __restrict__ Q, const float* __restrict__ K,
    const float* __restrict__ V, float* __restrict__ ctx)
{
    extern __shared__ char smem[];
    const uint32_t sb = smem_u32(smem);
    const int tid  = threadIdx.x;
    const int lane = tid & 31;
    const int wid  = tid >> 5;
    const int bh   = blockIdx.y;
    const int b    = bh >> 5;
    const int h    = bh & 31;
    const int qt   = blockIdx.x;
    const int q0   = qt * 128;

    const float* Qg = Q + ((size_t)bh * SEQ + q0) * HDIM;
    #pragma unroll
    for (int l = 0; l < 8; l++) {
        int id  = tid + l * 256;
        int row = id >> 4;
        int d4  = id & 15;
        uint32_t dst = sb + OFF_QS + (uint32_t)((d4 >> 3) * 16384 + row * 128
                        + (((d4 & 7) * 16) ^ ((row & 7) << 4)));
        CP16(dst, Qg + row * HDIM + d4 * 4);
    }
    CP_COMMIT();

    const uint32_t aRow = (uint32_t)((wid * 16 + (lane & 15)) * 128);
    const uint32_t bRowB = (uint32_t)((lane & 7) * 128);
    const uint32_t xorv = (uint32_t)((lane & 7) << 4);
    const uint32_t aseg = (uint32_t)((lane >> 4) * 16);
    const uint32_t bseg = (uint32_t)(((lane >> 3) & 1) * 16);
    const int gq = lane >> 2;
    const int qc = lane & 3;

    float o[8][4];
    #pragma unroll
    for (int ni = 0; ni < 8; ni++)
        #pragma unroll
        for (int e = 0; e < 4; e++) o[ni][e] = 0.f;
    float m0 = -1e30f, m1 = -1e30f, l0 = 0.f, l1 = 0.f;

    const int rowmin = q0 + wid * 16;
    const int rowmax = rowmin + 15;
    const int r0g = rowmin + gq;
    const int r1g = r0g + 8;
    const int nkt = 2 * qt + 2;
    const float scale = 0.125f;

    for (int kt = 0; kt < nkt; kt++) {
        const int k0 = kt * 64;
        __syncthreads();

        const float* Kg = K + ((size_t)bh * SEQ + k0) * HDIM;
        #pragma unroll
        for (int l = 0; l < 4; l++) {
            int id = tid + l * 256;
            int kk = id >> 4;
            int d4 = id & 15;
            uint32_t dst = sb + OFF_KS + (uint32_t)((d4 >> 3) * 8192 + kk * 128
                            + (((d4 & 7) * 16) ^ ((kk & 7) << 4)));
            CP16(dst, Kg + kk * HDIM + d4 * 4);
        }
        CP_COMMIT();

        const float* Vg = V + ((size_t)bh * SEQ + k0) * HDIM;
        #pragma unroll
        for (int l = 0; l < 4; l++) {
            int id = tid + l * 256;
            int kk = id >> 4;
            int d4 = id & 15;
            float4 vv = *reinterpret_cast<const float4*>(Vg + kk * HDIM + d4 * 4);
            #pragma unroll
            for (int i = 0; i < 4; i++) {
                int dd = d4 * 4 + i;
                uint32_t adr = sb + OFF_VT + (uint32_t)((kk >> 5) * 8192 + dd * 128
                                + (((kk & 31) * 4) ^ ((dd & 7) << 4)));
                float fv = (i == 0) ? vv.x : (i == 1) ? vv.y : (i == 2) ? vv.z : vv.w;
                asm volatile("st.shared.f32 [%0], %1;" :: "r"(adr), "f"(fv) : "memory");
            }
        }
        CP_WAIT0();
        __syncthreads();

        if (k0 <= rowmax) {
            float s[8][4];
            #pragma unroll
            for (int ni = 0; ni < 8; ni++)
                #pragma unroll
                for (int e = 0; e < 4; e++) s[ni][e] = 0.f;

            #pragma unroll
            for (int pn = 0; pn < 2; pn++) {
                const uint32_t qb = sb + OFF_QS + pn * 16384u;
                const uint32_t kb_ = sb + OFF_KS + pn * 8192u;
                #pragma unroll
                for (int k8 = 0; k8 < 4; k8++) {
                    const uint32_t kb = (uint32_t)(k8 * 32);
                    uint32_t af[4];
                    ldsm_x4(af, qb + aRow + ((kb + aseg) ^ xorv));
                    #pragma unroll
                    for (int ni = 0; ni < 8; ni++) {
                        uint32_t bf[2];
                        ldsm_x2(bf, kb_ + bRowB + ni * 1024u + ((kb + bseg) ^ xorv));
                        mma_tf32(s[ni], af, bf);
                    }
                }
            }

            const bool need_mask = (k0 + 63 > rowmin);
            #pragma unroll
            for (int ni = 0; ni < 8; ni++) {
                int c0 = k0 + ni * 8 + qc * 2;
                if (need_mask) {
                    s[ni][0] = (c0     > r0g) ? -1e30f : s[ni][0] * scale;
                    s[ni][1] = (c0 + 1 > r0g) ? -1e30f : s[ni][1] * scale;
                    s[ni][2] = (c0     > r1g) ? -1e30f : s[ni][2] * scale;
                    s[ni][3] = (c0 + 1 > r1g) ? -1e30f : s[ni][3] * scale;
                } else {
                    s[ni][0] *= scale; s[ni][1] *= scale;
                    s[ni][2] *= scale; s[ni][3] *= scale;
                }
            }

            float mx0 = -1e30f, mx1 = -1e30f;
            #pragma unroll
            for (int ni = 0; ni < 8; ni++) {
                mx0 = fmaxf(mx0, fmaxf(s[ni][0], s[ni][1]));
                mx1 = fmaxf(mx1, fmaxf(s[ni][2], s[ni][3]));
            }
            mx0 = fmaxf(mx0, __shfl_xor_sync(0xffffffffu, mx0, 1));
            mx0 = fmaxf(mx0, __shfl_xor_sync(0xffffffffu, mx0, 2));
            mx1 = fmaxf(mx1, __shfl_xor_sync(0xffffffffu, mx1, 1));
            mx1 = fmaxf(mx1, __shfl_xor_sync(0xffffffffu, mx1, 2));

            const float mn0 = fmaxf(m0, mx0);
            const float mn1 = fmaxf(m1, mx1);
            const float corr0 = __expf(m0 - mn0);
            const float corr1 = __expf(m1 - mn1);

            float rs0 = 0.f, rs1 = 0.f;
            const int prow0 = wid * 16 + gq;
            #pragma unroll
            for (int ni = 0; ni < 8; ni++) {
                float p0 = __expf(s[ni][0] - mn0);
                float p1 = __expf(s[ni][1] - mn0);
                float p2 = __expf(s[ni][2] - mn1);
                float p3 = __expf(s[ni][3] - mn1);
                rs0 += p0 + p1;
                rs1 += p2 + p3;
                int col = ni * 8 + qc * 2;
                uint32_t pa = sb + OFF_PS + (uint32_t)((col >> 5) * 16384
                               + prow0 * 128 + (((col & 31) * 4) ^ ((gq & 7) << 4)));
                asm volatile("st.shared.v2.f32 [%0], {%1,%2};"
                    :: "r"(pa), "f"(cvt_tf32_f(p0)), "f"(cvt_tf32_f(p1)) : "memory");
                asm volatile("st.shared.v2.f32 [%0], {%1,%2};"
                    :: "r"(pa + 8 * 128), "f"(cvt_tf32_f(p2)), "f"(cvt_tf32_f(p3)) : "memory");
            }
            rs0 += __shfl_xor_sync(0xffffffffu, rs0, 1);
            rs0 += __shfl_xor_sync(0xffffffffu, rs0, 2);
            rs1 += __shfl_xor_sync(0xffffffffu, rs1, 1);
            rs1 += __shfl_xor_sync(0xffffffffu, rs1, 2);

            l0 = l0 * corr0 + rs0;
            l1 = l1 * corr1 + rs1;
            m0 = mn0; m1 = mn1;

            #pragma unroll
            for (int ni = 0; ni < 8; ni++) {
                o[ni][0] *= corr0; o[ni][1] *= corr0;
                o[ni][2] *= corr1; o[ni][3] *= corr1;
            }
            __syncwarp();

            #pragma unroll
            for (int pn = 0; pn < 2; pn++) {
                const uint32_t pb = sb + OFF_PS + pn * 16384u;
                const uint32_t vb = sb + OFF_VT + pn * 8192u;
                #pragma unroll
                for (int k8 = 0; k8 < 4; k8++) {
                    const uint32_t kb = (uint32_t)(k8 * 32);
                    uint32_t af[4];
                    ldsm_x4(af, pb + aRow + ((kb + aseg) ^ xorv));
                    #pragma unroll
                    for (int ni = 0; ni < 8; ni++) {
                        uint32_t bf[2];
                        ldsm_x2(bf, vb + bRowB + ni * 1024u + ((kb + bseg) ^ xorv));
                        mma_tf32(o[ni], af, bf);
                    }
                }
            }
        }
    }

    const float inv0 = 1.f / l0;
    const float inv1 = 1.f / l1;
    const int t0 = q0 + wid * 16 + gq;
    float* c0p = ctx + ((size_t)b * SEQ + t0) * CDIM + h * HDIM;
    float* c1p = c0p + 8 * (size_t)CDIM;
    #pragma unroll
    for (int ni = 0; ni < 8; ni++) {
        int d = ni * 8 + qc * 2;
        float2 w0 = make_float2(cvt_tf32_f(o[ni][0] * inv0), cvt_tf32_f(o[ni][1] * inv0));
        float2 w1 = make_float2(cvt_tf32_f(o[ni][2] * inv1), cvt_tf32_f(o[ni][3] * inv1));
        *reinterpret_cast<float2*>(c0p + d) = w0;
        *reinterpret_cast<float2*>(c1p + d) = w1;
    }
}

// ---------------------------------------------------------------------------
extern "C" void kernel_launch(void* const* d_in, const int* in_sizes, int n_in,
                              void* d_out, int out_size)
{
    const float* x      = (const float*)d_in[0];
    const float* rope   = (const float*)d_in[3];
    const float* Wqkv_w = (const float*)d_in[4];
    const float* Wqkv_b = (const float*)d_in[5];
    const float* out_w  = (const float*)d_in[6];
    const float* out_b  = (const float*)d_in[7];
    float* out = (float*)d_out;

    float *qkv, *q, *k, *v, *xc, *w1, *w2;
    cudaGetSymbolAddress((void**)&qkv, g_qkv);
    cudaGetSymbolAddress((void**)&q,   g_q);
    cudaGetSymbolAddress((void**)&k,   g_k);
    cudaGetSymbolAddress((void**)&v,   g_v);
    cudaGetSymbolAddress((void**)&xc,  g_xc);
    cudaGetSymbolAddress((void**)&w1,  g_w1);
    cudaGetSymbolAddress((void**)&w2,  g_w2);
    float* ctx = qkv;

    cudaFuncSetAttribute(gemm_tf32, cudaFuncAttributeMaxDynamicSharedMemorySize, GEMM_SMEM);
    cudaFuncSetAttribute(gemm_tf32, cudaFuncAttributePreferredSharedMemoryCarveout, 100);
    cudaFuncSetAttribute(attn_tc, cudaFuncAttributeMaxDynamicSharedMemorySize, ATTN_SMEM2);
    cudaFuncSetAttribute(attn_tc, cudaFuncAttributePreferredSharedMemoryCarveout, 100);

    // 0) pre-round GEMM operands to tf32 bit patterns
    cvt_tf32_copy<<<(MROWS * CDIM / 4 + 255) / 256, 256>>>(x,      xc, MROWS * CDIM / 4);
    cvt_tf32_copy<<<(QKVN  * CDIM / 4 + 255) / 256, 256>>>(Wqkv_w, w1, QKVN  * CDIM / 4);
    cvt_tf32_copy<<<(CDIM  * CDIM / 4 + 255) / 256, 256>>>(out_w,  w2, CDIM  * CDIM / 4);

    // 1) QKV projection (tf32 tensor cores, 128x256 tiles)
    gemm_tf32<<<dim3(QKVN / BN2, MROWS / 128), 256, GEMM_SMEM>>>(
        xc, w1, Wqkv_b, qkv, MROWS, QKVN, CDIM);

    // 2) RoPE + transpose (q/k/v tf32-rounded)
    rope_transpose<<<(BATCH * SEQ * NHEAD * HDIM) / 256, 256>>>(qkv, rope, q, k, v);

    // 3) causal attention on tensor cores
    attn_tc<<<dim3(SEQ / 128, BATCH * NHEAD), 256, ATTN_SMEM2>>>(q, k, v, ctx);

    // 4) output projection (tf32 tensor cores, 128x256 tiles)
    gemm_tf32<<<dim3(CDIM / BN2, MROWS / 128), 256, GEMM_SMEM>>>(
        ctx, w2, out_b, out, MROWS, CDIM, CDIM);
}

// round 10
// speedup vs baseline: 1.1401x; 1.1401x over previous
#include <cuda_runtime.h>
#include <cuda_bf16.h>
#include <cstdint>

// Problem constants
#define BATCH 4
#define SEQ   1024
#define CDIM  2048
#define NHEAD 32
#define HDIM  64
#define QKVN  (3*CDIM)          // 6144
#define MROWS (BATCH*SEQ)       // 4096

// Scratch (device globals: allocation-free rule)
__device__ float g_ctx[(size_t)MROWS * CDIM];
__device__ float g_q[(size_t)BATCH*NHEAD*SEQ*HDIM];
__device__ float g_k[(size_t)BATCH*NHEAD*SEQ*HDIM];
__device__ float g_v[(size_t)BATCH*NHEAD*SEQ*HDIM];
// tf32-pre-rounded operand copies
__device__ float g_xc[(size_t)MROWS * CDIM];
__device__ float g_w1[(size_t)QKVN * CDIM];
__device__ float g_w2[(size_t)CDIM * CDIM];

// ---------------------------------------------------------------------------
// helpers
// ---------------------------------------------------------------------------
__device__ __forceinline__ uint32_t smem_u32(const void* p) {
    uint32_t a;
    asm("{ .reg .u64 t; cvta.to.shared.u64 t, %1; cvt.u32.u64 %0, t; }" : "=r"(a) : "l"(p));
    return a;
}
#define CP16(dst, src) \
    asm volatile("cp.async.cg.shared.global [%0], [%1], 16;" :: "r"(dst), "l"(src) : "memory")
#define CP_COMMIT() asm volatile("cp.async.commit_group;" ::: "memory")
#define CP_WAIT1()  asm volatile("cp.async.wait_group 1;" ::: "memory")
#define CP_WAIT0()  asm volatile("cp.async.wait_group 0;" ::: "memory")

__device__ __forceinline__ void ldsm_x4(uint32_t a[4], uint32_t addr) {
    asm volatile("ldmatrix.sync.aligned.m8n8.x4.shared.b16 {%0,%1,%2,%3}, [%4];"
        : "=r"(a[0]), "=r"(a[1]), "=r"(a[2]), "=r"(a[3]) : "r"(addr));
}
__device__ __forceinline__ void ldsm_x2(uint32_t a[2], uint32_t addr) {
    asm volatile("ldmatrix.sync.aligned.m8n8.x2.shared.b16 {%0,%1}, [%2];"
        : "=r"(a[0]), "=r"(a[1]) : "r"(addr));
}
__device__ __forceinline__ float cvt_tf32_f(float x) {
    uint32_t r;
    asm("cvt.rna.tf32.f32 %0, %1;" : "=r"(r) : "f"(x));
    return __uint_as_float(r);
}
__device__ __forceinline__ void mma_tf32(float c[4], const uint32_t a[4], const uint32_t b[2]) {
    asm volatile(
        "mma.sync.aligned.m16n8k8.row.col.f32.tf32.tf32.f32 "
        "{%0,%1,%2,%3}, {%4,%5,%6,%7}, {%8,%9}, {%0,%1,%2,%3};"
        : "+f"(c[0]), "+f"(c[1]), "+f"(c[2]), "+f"(c[3])
        : "r"(a[0]), "r"(a[1]), "r"(a[2]), "r"(a[3]), "r"(b[0]), "r"(b[1]));
}

// ---------------------------------------------------------------------------
// tf32 pre-round pass: out[i] = rna_tf32(in[i])  (idempotent)
// ---------------------------------------------------------------------------
__global__ void __launch_bounds__(256) cvt_tf32_copy(
    const float* __restrict__ in, float* __restrict__ out, int n4)
{
    int i = blockIdx.x * 256 + threadIdx.x;
    if (i < n4) {
        float4 v = reinterpret_cast<const float4*>(in)[i];
        v.x = cvt_tf32_f(v.x); v.y = cvt_tf32_f(v.y);
        v.z = cvt_tf32_f(v.z); v.w = cvt_tf32_f(v.w);
        reinterpret_cast<float4*>(out)[i] = v;
    }
}

// ---------------------------------------------------------------------------
// TF32 mma.sync GEMM (R8 shape: 128x128 CTA, 64x32 warp tile, 8 warps, BK=32,
// 3-stage cp.async, 2 CTAs/SM). Two epilogues:
//  - standard: C = acc + bias  (out-projection; qo == nullptr)
//  - fused QKV: bias + RoPE in fp32, scatter tf32-rounded q/k/v [B,H,T,hd]
// ---------------------------------------------------------------------------
#define BKC 32
#define STAGE_BYTES 32768
#define GEMM_SMEM (3 * STAGE_BYTES)

__global__ void __launch_bounds__(256, 2) gemm_tf32(
    const float* __restrict__ A, const float* __restrict__ B,
    const float* __restrict__ bias, float* __restrict__ C,
    const float* __restrict__ ropeG,
    float* __restrict__ qo, float* __restrict__ ko, float* __restrict__ vo,
    int M, int N, int K)
{
    extern __shared__ char smem[];
    const uint32_t sb = smem_u32(smem);
    const int tid  = threadIdx.x;
    const int lane = tid & 31;
    const int wid  = tid >> 5;
    const int row0 = blockIdx.y * 128;
    const int col0 = blockIdx.x * 128;
    const int wm = (wid >> 2) * 64;
    const int wn = (wid & 3) * 32;

    const int r = tid >> 3;
    const int c = tid & 7;
    const float* aSrc = A + (size_t)(row0 + r) * K + c * 4;
    const float* bSrc = B + (size_t)(col0 + r) * K + c * 4;
    uint32_t dOff[4];
    #pragma unroll
    for (int l = 0; l < 4; l++) {
        int row = r + 32 * l;
        dOff[l] = (uint32_t)(row * 128 + ((c * 16) ^ ((row & 7) << 4)));
    }

    const int nk = K / BKC;

    uint32_t aRow[4], bRow[4];
    #pragma unroll
    for (int mi = 0; mi < 4; mi++) aRow[mi] = (uint32_t)((wm + mi * 16 + (lane & 15)) * 128);
    #pragma unroll
    for (int ni = 0; ni < 4; ni++) bRow[ni] = (uint32_t)((wn + ni * 8 + (lane & 7)) * 128);
    const uint32_t xorv = (uint32_t)((lane & 7) << 4);
    const uint32_t aseg = (uint32_t)((lane >> 4) * 16);
    const uint32_t bseg = (uint32_t)(((lane >> 3) & 1) * 16);

    float acc[16][4];
    #pragma unroll
    for (int t = 0; t < 16; t++)
        #pragma unroll
        for (int j = 0; j < 4; j++) acc[t][j] = 0.f;

    #pragma unroll
    for (int p = 0; p < 2; p++) {
        uint32_t base = sb + p * STAGE_BYTES;
        size_t koff = (size_t)p * BKC;
        #pragma unroll
        for (int l = 0; l < 4; l++) CP16(base + dOff[l],         aSrc + (size_t)l * 32 * K + koff);
        #pragma unroll
        for (int l = 0; l < 4; l++) CP16(base + 16384 + dOff[l], bSrc + (size_t)l * 32 * K + koff);
        CP_COMMIT();
    }

    int sCur = 0, sNext = 2;
    for (int i = 0; i < nk; i++) {
        CP_WAIT1();
        __syncthreads();

        if (i + 2 < nk) {
            uint32_t base = sb + sNext * STAGE_BYTES;
            size_t koff = (size_t)(i + 2) * BKC;
            #pragma unroll
            for (int l = 0; l < 4; l++) CP16(base + dOff[l],         aSrc + (size_t)l * 32 * K + koff);
            #pragma unroll
            for (int l = 0; l < 4; l++) CP16(base + 16384 + dOff[l], bSrc + (size_t)l * 32 * K + koff);
        }
        CP_COMMIT();

        const uint32_t aBase = sb + sCur * STAGE_BYTES;
        const uint32_t bBase = aBase + 16384;

        #pragma unroll
        for (int ks = 0; ks < 4; ks++) {
            const uint32_t kb = (uint32_t)(ks * 32);
            uint32_t af[4][4], bf[4][2];
            #pragma unroll
            for (int mi = 0; mi < 4; mi++)
                ldsm_x4(af[mi], aBase + aRow[mi] + ((kb + aseg) ^ xorv));
            #pragma unroll
            for (int ni = 0; ni < 4; ni++)
                ldsm_x2(bf[ni], bBase + bRow[ni] + ((kb + bseg) ^ xorv));
            #pragma unroll
            for (int mi = 0; mi < 4; mi++)
                #pragma unroll
                for (int ni = 0; ni < 4; ni++)
                    mma_tf32(acc[mi * 4 + ni], af[mi], bf[ni]);
        }

        sCur = (sCur + 1) % 3;
        sNext = (sNext + 1) % 3;
    }

    const int gq = lane >> 2;
    const int qc = lane & 3;

    if (qo == nullptr) {
        // standard epilogue (out-projection)
        #pragma unroll
        for (int mi = 0; mi < 4; mi++) {
            #pragma unroll
            for (int ni = 0; ni < 4; ni++) {
                const float* ac = acc[mi * 4 + ni];
                int colb = col0 + wn + ni * 8 + qc * 2;
                float b0 = __ldg(&bias[colb]);
                float b1 = __ldg(&bias[colb + 1]);
                size_t base0 = (size_t)(row0 + wm + mi * 16 + gq) * N + colb;
                C[base0]         = ac[0] + b0;
                C[base0 + 1]     = ac[1] + b1;
                C[base0 + 8 * (size_t)N]     = ac[2] + b0;
                C[base0 + 8 * (size_t)N + 1] = ac[3] + b1;
            }
        }
        return;
    }

    // ---- fused QKV epilogue: bias + RoPE + scatter to q/k/v [B,H,T,hd] ----
    const int colband = col0 + wn;          // multiple of 32, < 6144
    const int region  = colband >> 11;      // 0=q 1=k 2=v
    const int cb      = colband & 2047;     // col within region
    const int h       = cb >> 6;
    const int hb      = cb & 63;            // 0 (rope half) or 32 (pass half)
    float* dst = (region == 0) ? qo : (region == 1) ? ko : vo;

    #pragma unroll
    for (int mi = 0; mi < 4; mi++) {
        const int rr = row0 + wm + mi * 16 + gq;
        const int bb = rr >> 10;
        const int t  = rr & 1023;
        const size_t base0 = ((size_t)(bb * NHEAD + h) * SEQ + t) * HDIM;
        const size_t base1 = base0 + 8 * HDIM;   // row rr+8 (same b, t+8)

        if (region == 2 || hb == 32) {
            // passthrough: v everywhere, or d in [32,64) of q/k
            #pragma unroll
            for (int ni = 0; ni < 4; ni++) {
                const float* ac = acc[mi * 4 + ni];
                int dc = ni * 8 + qc * 2;
                int d  = hb + dc;
                float b0 = __ldg(&bias[colband + dc]);
                float b1 = __ldg(&bias[colband + dc + 1]);
                dst[base0 + d]     = cvt_tf32_f(ac[0] + b0);
                dst[base0 + d + 1] = cvt_tf32_f(ac[1] + b1);
                dst[base1 + d]     = cvt_tf32_f(ac[2] + b0);
                dst[base1 + d + 1] = cvt_tf32_f(ac[3] + b1);
            }
        } else {
            // rope: d in [0,16) pairs with d+16 (fragments ni and ni+2)
            #pragma unroll
            for (int ni = 0; ni < 2; ni++) {
                const float* a1 = acc[mi * 4 + ni];       // dims d, d+1
                const float* a2 = acc[mi * 4 + ni + 2];   // dims d+16, d+17
                const int d = ni * 8 + qc * 2;            // 0..15
                float bl[2], bh2[2];
                bl[0]  = __ldg(&bias[colband + d]);
                bl[1]  = __ldg(&bias[colband + d + 1]);
                bh2[0] = __ldg(&bias[colband + d + 16]);
                bh2[1] = __ldg(&bias[colband + d + 17]);
                #pragma unroll
                for (int e = 0; e < 2; e++) {
                    const int j = d + e;
                    float2 cs0 = *reinterpret_cast<const float2*>(&ropeG[((size_t)t * 16 + j) * 2]);
                    float2 cs1 = *reinterpret_cast<const float2*>(&ropeG[((size_t)(t + 8) * 16 + j) * 2]);
                    float x1r0 = a1[e]     + bl[e];
                    float x2r0 = a2[e]     + bh2[e];
                    float x1r1 = a1[e + 2] + bl[e];
                    float x2r1 = a2[e + 2] + bh2[e];
                    dst[base0 + j]      = cvt_tf32_f(x1r0 * cs0.x - x2r0 * cs0.y);
                    dst[base0 + j + 16] = cvt_tf32_f(x2r0 * cs0.x + x1r0 * cs0.y);
                    dst[base1 + j]      = cvt_tf32_f(x1r1 * cs1.x - x2r1 * cs1.y);
                    dst[base1 + j + 16] = cvt_tf32_f(x2r1 * cs1.x + x1r1 * cs1.y);
                }
            }
        }
    }
}

// ---------------------------------------------------------------------------
// Tensor-core causal flash attention (tf32 mma.sync). Unchanged from R8.
// ---------------------------------------------------------------------------
#define ATTN_SMEM2 98304
#define OFF_QS 0u
#define OFF_KS 32768u
#define OFF_VT 49152u
#define OFF_PS 65536u

__global__ void __launch_bounds__(256) attn_tc(
    const float* __restrict__ Q, const float* __restrict__ K,
    const float* __restrict__ V, float* __restrict__ ctx)
{
    extern __shared__ char smem[];
    const uint32_t sb = smem_u32(smem);
    const int tid  = threadIdx.x;
    const int lane = tid & 31;
    const int wid  = tid >> 5;
    const int bh   = blockIdx.y;
    const int b    = bh >> 5;
    const int h    = bh & 31;
    const int qt   = blockIdx.x;
    const int q0   = qt * 128;

    const float* Qg = Q + ((size_t)bh * SEQ + q0) * HDIM;
    #pragma unroll
    for (int l = 0; l < 8; l++) {
        int id  = tid + l * 256;
        int row = id >> 4;
        int d4  = id & 15;
        uint32_t dst = sb + OFF_QS + (uint32_t)((d4 >> 3) * 16384 + row * 128
                        + (((d4 & 7) * 16) ^ ((row & 7) << 4)));
        CP16(dst, Qg + row * HDIM + d4 * 4);
    }
    CP_COMMIT();

    const uint32_t aRow = (uint32_t)((wid * 16 + (lane & 15)) * 128);
    const uint32_t bRowB = (uint32_t)((lane & 7) * 128);
    const uint32_t xorv = (uint32_t)((lane & 7) << 4);
    const uint32_t aseg = (uint32_t)((lane >> 4) * 16);
    const uint32_t bseg = (uint32_t)(((lane >> 3) & 1) * 16);
    const int gq = lane >> 2;
    const int qc = lane & 3;

    float o[8][4];
    #pragma unroll
    for (int ni = 0; ni < 8; ni++)
        #pragma unroll
        for (int e = 0; e < 4; e++) o[ni][e] = 0.f;
    float m0 = -1e30f, m1 = -1e30f, l0 = 0.f, l1 = 0.f;

    const int rowmin = q0 + wid * 16;
    const int rowmax = rowmin + 15;
    const int r0g = rowmin + gq;
    const int r1g = r0g + 8;
    const int nkt = 2 * qt + 2;
    const float scale = 0.125f;

    for (int kt = 0; kt < nkt; kt++) {
        const int k0 = kt * 64;
        __syncthreads();

        const float* Kg = K + ((size_t)bh * SEQ + k0) * HDIM;
        #pragma unroll
        for (int l = 0; l < 4; l++) {
            int id = tid + l * 256;
            int kk = id >> 4;
            int d4 = id & 15;
            uint32_t dst = sb + OFF_KS + (uint32_t)((d4 >> 3) * 8192 + kk * 128
                            + (((d4 & 7) * 16) ^ ((kk & 7) << 4)));
            CP16(dst, Kg + kk * HDIM + d4 * 4);
        }
        CP_COMMIT();

        const float* Vg = V + ((size_t)bh * SEQ + k0) * HDIM;
        #pragma unroll
        for (int l = 0; l < 4; l++) {
            int id = tid + l * 256;
            int kk = id >> 4;
            int d4 = id & 15;
            float4 vv = *reinterpret_cast<const float4*>(Vg + kk * HDIM + d4 * 4);
            #pragma unroll
            for (int i = 0; i < 4; i++) {
                int dd = d4 * 4 + i;
                uint32_t adr = sb + OFF_VT + (uint32_t)((kk >> 5) * 8192 + dd * 128
                                + (((kk & 31) * 4) ^ ((dd & 7) << 4)));
                float fv = (i == 0) ? vv.x : (i == 1) ? vv.y : (i == 2) ? vv.z : vv.w;
                asm volatile("st.shared.f32 [%0], %1;" :: "r"(adr), "f"(fv) : "memory");
            }
        }
        CP_WAIT0();
        __syncthreads();

        if (k0 <= rowmax) {
            float s[8][4];
            #pragma unroll
            for (int ni = 0; ni < 8; ni++)
                #pragma unroll
                for (int e = 0; e < 4; e++) s[ni][e] = 0.f;

            #pragma unroll
            for (int pn = 0; pn < 2; pn++) {
                const uint32_t qb = sb + OFF_QS + pn * 16384u;
                const uint32_t kb_ = sb + OFF_KS + pn * 8192u;
                #pragma unroll
                for (int k8 = 0; k8 < 4; k8++) {
                    const uint32_t kb = (uint32_t)(k8 * 32);
                    uint32_t af[4];
                    ldsm_x4(af, qb + aRow + ((kb + aseg) ^ xorv));
                    #pragma unroll
                    for (int ni = 0; ni < 8; ni++) {
                        uint32_t bf[2];
                        ldsm_x2(bf, kb_ + bRowB + ni * 1024u + ((kb + bseg) ^ xorv));
                        mma_tf32(s[ni], af, bf);
                    }
                }
            }

            const bool need_mask = (k0 + 63 > rowmin);
            #pragma unroll
            for (int ni = 0; ni < 8; ni++) {
                int c0 = k0 + ni * 8 + qc * 2;
                if (need_mask) {
                    s[ni][0] = (c0     > r0g) ? -1e30f : s[ni][0] * scale;
                    s[ni][1] = (c0 + 1 > r0g) ? -1e30f : s[ni][1] * scale;
                    s[ni][2] = (c0     > r1g) ? -1e30f : s[ni][2] * scale;
                    s[ni][3] = (c0 + 1 > r1g) ? -1e30f : s[ni][3] * scale;
                } else {
                    s[ni][0] *= scale; s[ni][1] *= scale;
                    s[ni][2] *= scale; s[ni][3] *= scale;
                }
            }

            float mx0 = -1e30f, mx1 = -1e30f;
            #pragma unroll
            for (int ni = 0; ni < 8; ni++) {
                mx0 = fmaxf(mx0, fmaxf(s[ni][0], s[ni][1]));
                mx1 = fmaxf(mx1, fmaxf(s[ni][2], s[ni][3]));
            }
            mx0 = fmaxf(mx0, __shfl_xor_sync(0xffffffffu, mx0, 1));
            mx0 = fmaxf(mx0, __shfl_xor_sync(0xffffffffu, mx0, 2));
            mx1 = fmaxf(mx1, __shfl_xor_sync(0xffffffffu, mx1, 1));
            mx1 = fmaxf(mx1, __shfl_xor_sync(0xffffffffu, mx1, 2));

            const float mn0 = fmaxf(m0, mx0);
            const float mn1 = fmaxf(m1, mx1);
            const float corr0 = __expf(m0 - mn0);
            const float corr1 = __expf(m1 - mn1);

            float rs0 = 0.f, rs1 = 0.f;
            const int prow0 = wid * 16 + gq;
            #pragma unroll
            for (int ni = 0; ni < 8; ni++) {
                float p0 = __expf(s[ni][0] - mn0);
                float p1 = __expf(s[ni][1] - mn0);
                float p2 = __expf(s[ni][2] - mn1);
                float p3 = __expf(s[ni][3] - mn1);
                rs0 += p0 + p1;
                rs1 += p2 + p3;
                int col = ni * 8 + qc * 2;
                uint32_t pa = sb + OFF_PS + (uint32_t)((col >> 5) * 16384
                               + prow0 * 128 + (((col & 31) * 4) ^ ((gq & 7) << 4)));
                asm volatile("st.shared.v2.f32 [%0], {%1,%2};"
                    :: "r"(pa), "f"(cvt_tf32_f(p0)), "f"(cvt_tf32_f(p1)) : "memory");
                asm volatile("st.shared.v2.f32 [%0], {%1,%2};"
                    :: "r"(pa + 8 * 128), "f"(cvt_tf32_f(p2)), "f"(cvt_tf32_f(p3)) : "memory");
            }
            rs0 += __shfl_xor_sync(0xffffffffu, rs0, 1);
            rs0 += __shfl_xor_sync(0xffffffffu, rs0, 2);
            rs1 += __shfl_xor_sync(0xffffffffu, rs1, 1);
            rs1 += __shfl_xor_sync(0xffffffffu, rs1, 2);

            l0 = l0 * corr0 + rs0;
            l1 = l1 * corr1 + rs1;
            m0 = mn0; m1 = mn1;

            #pragma unroll
            for (int ni = 0; ni < 8; ni++) {
                o[ni][0] *= corr0; o[ni][1] *= corr0;
                o[ni][2] *= corr1; o[ni][3] *= corr1;
            }
            __syncwarp();

            #pragma unroll
            for (int pn = 0; pn < 2; pn++) {
                const uint32_t pb = sb + OFF_PS + pn * 16384u;
                const uint32_t vb = sb + OFF_VT + pn * 8192u;
                #pragma unroll
                for (int k8 = 0; k8 < 4; k8++) {
                    const uint32_t kb = (uint32_t)(k8 * 32);
                    uint32_t af[4];
                    ldsm_x4(af, pb + aRow + ((kb + aseg) ^ xorv));
                    #pragma unroll
                    for (int ni = 0; ni < 8; ni++) {
                        uint32_t bf[2];
                        ldsm_x2(bf, vb + bRowB + ni * 1024u + ((kb + bseg) ^ xorv));
                        mma_tf32(o[ni], af, bf);
                    }
                }
            }
        }
    }

    const float inv0 = 1.f / l0;
    const float inv1 = 1.f / l1;
    const int t0 = q0 + wid * 16 + gq;
    float* c0p = ctx + ((size_t)b * SEQ + t0) * CDIM + h * HDIM;
    float* c1p = c0p + 8 * (size_t)CDIM;
    #pragma unroll
    for (int ni = 0; ni < 8; ni++) {
        int d = ni * 8 + qc * 2;
        float2 w0 = make_float2(cvt_tf32_f(o[ni][0] * inv0), cvt_tf32_f(o[ni][1] * inv0));
        float2 w1 = make_float2(cvt_tf32_f(o[ni][2] * inv1), cvt_tf32_f(o[ni][3] * inv1));
        *reinterpret_cast<float2*>(c0p + d) = w0;
        *reinterpret_cast<float2*>(c1p + d) = w1;
    }
}

// ---------------------------------------------------------------------------
extern "C" void kernel_launch(void* const* d_in, const int* in_sizes, int n_in,
                              void* d_out, int out_size)
{
    const float* x      = (const float*)d_in[0];
    const float* rope   = (const float*)d_in[3];
    const float* Wqkv_w = (const float*)d_in[4];
    const float* Wqkv_b = (const float*)d_in[5];
    const float* out_w  = (const float*)d_in[6];
    const float* out_b  = (const float*)d_in[7];
    float* out = (float*)d_out;

    float *ctx, *q, *k, *v, *xc, *w1, *w2;
    cudaGetSymbolAddress((void**)&ctx, g_ctx);
    cudaGetSymbolAddress((void**)&q,   g_q);
    cudaGetSymbolAddress((void**)&k,   g_k);
    cudaGetSymbolAddress((void**)&v,   g_v);
    cudaGetSymbolAddress((void**)&xc,  g_xc);
    cudaGetSymbolAddress((void**)&w1,  g_w1);
    cudaGetSymbolAddress((void**)&w2,  g_w2);

    cudaFuncSetAttribute(gemm_tf32, cudaFuncAttributeMaxDynamicSharedMemorySize, GEMM_SMEM);
    cudaFuncSetAttribute(gemm_tf32, cudaFuncAttributePreferredSharedMemoryCarveout, 100);
    cudaFuncSetAttribute(attn_tc, cudaFuncAttributeMaxDynamicSharedMemorySize, ATTN_SMEM2);
    cudaFuncSetAttribute(attn_tc, cudaFuncAttributePreferredSharedMemoryCarveout, 100);

    // 0) pre-round GEMM operands to tf32 bit patterns
    cvt_tf32_copy<<<(MROWS * CDIM / 4 + 255) / 256, 256>>>(x,      xc, MROWS * CDIM / 4);
    cvt_tf32_copy<<<(QKVN  * CDIM / 4 + 255) / 256, 256>>>(Wqkv_w, w1, QKVN  * CDIM / 4);
    cvt_tf32_copy<<<(CDIM  * CDIM / 4 + 255) / 256, 256>>>(out_w,  w2, CDIM  * CDIM / 4);

    // 1) QKV projection fused with bias + RoPE + q/k/v scatter
    gemm_tf32<<<dim3(QKVN / 128, MROWS / 128), 256, GEMM_SMEM>>>(
        xc, w1, Wqkv_b, nullptr, rope, q, k, v, MROWS, QKVN, CDIM);

    // 2) causal attention on tensor cores
    attn_tc<<<dim3(SEQ / 128, BATCH * NHEAD), 256, ATTN_SMEM2>>>(q, k, v, ctx);

    // 3) output projection (standard epilogue)
    gemm_tf32<<<dim3(CDIM / 128, MROWS / 128), 256, GEMM_SMEM>>>(
        ctx, w2, out_b, out, nullptr, nullptr, nullptr, nullptr, MROWS, CDIM, CDIM);
}

// round 11
// speedup vs baseline: 1.1550x; 1.0131x over previous
#include <cuda_runtime.h>
#include <cuda_bf16.h>
#include <cstdint>

// Problem constants
#define BATCH 4
#define SEQ   1024
#define CDIM  2048
#define NHEAD 32
#define HDIM  64
#define QKVN  (3*CDIM)          // 6144
#define MROWS (BATCH*SEQ)       // 4096

// Scratch (device globals: allocation-free rule)
__device__ float g_ctx[(size_t)MROWS * CDIM];
__device__ float g_q[(size_t)BATCH*NHEAD*SEQ*HDIM];
__device__ float g_k[(size_t)BATCH*NHEAD*SEQ*HDIM];
__device__ float g_v[(size_t)BATCH*NHEAD*SEQ*HDIM];
// tf32-pre-rounded operand copies
__device__ float g_xc[(size_t)MROWS * CDIM];
__device__ float g_w1[(size_t)QKVN * CDIM];
__device__ float g_w2[(size_t)CDIM * CDIM];

// ---------------------------------------------------------------------------
// helpers
// ---------------------------------------------------------------------------
__device__ __forceinline__ uint32_t smem_u32(const void* p) {
    uint32_t a;
    asm("{ .reg .u64 t; cvta.to.shared.u64 t, %1; cvt.u32.u64 %0, t; }" : "=r"(a) : "l"(p));
    return a;
}
#define CP16(dst, src) \
    asm volatile("cp.async.cg.shared.global [%0], [%1], 16;" :: "r"(dst), "l"(src) : "memory")
#define CP_COMMIT() asm volatile("cp.async.commit_group;" ::: "memory")
#define CP_WAIT1()  asm volatile("cp.async.wait_group 1;" ::: "memory")
#define CP_WAIT0()  asm volatile("cp.async.wait_group 0;" ::: "memory")

__device__ __forceinline__ void ldsm_x4(uint32_t a[4], uint32_t addr) {
    asm volatile("ldmatrix.sync.aligned.m8n8.x4.shared.b16 {%0,%1,%2,%3}, [%4];"
        : "=r"(a[0]), "=r"(a[1]), "=r"(a[2]), "=r"(a[3]) : "r"(addr));
}
__device__ __forceinline__ float cvt_tf32_f(float x) {
    uint32_t r;
    asm("cvt.rna.tf32.f32 %0, %1;" : "=r"(r) : "f"(x));
    return __uint_as_float(r);
}
__device__ __forceinline__ void mma_tf32(float c[4], const uint32_t a[4], const uint32_t b[2]) {
    asm volatile(
        "mma.sync.aligned.m16n8k8.row.col.f32.tf32.tf32.f32 "
        "{%0,%1,%2,%3}, {%4,%5,%6,%7}, {%8,%9}, {%0,%1,%2,%3};"
        : "+f"(c[0]), "+f"(c[1]), "+f"(c[2]), "+f"(c[3])
        : "r"(a[0]), "r"(a[1]), "r"(a[2]), "r"(a[3]), "r"(b[0]), "r"(b[1]));
}

// ---------------------------------------------------------------------------
// merged tf32 pre-round pass over x, Wqkv_w, out_w (single launch)
// ---------------------------------------------------------------------------
#define N4_X  (MROWS * CDIM / 4)
#define N4_W1 (QKVN * CDIM / 4)
#define N4_W2 (CDIM * CDIM / 4)

__global__ void __launch_bounds__(256) cvt_tf32_all(
    const float* __restrict__ x,  float* __restrict__ xc,
    const float* __restrict__ w1i, float* __restrict__ w1o,
    const float* __restrict__ w2i, float* __restrict__ w2o)
{
    int i = blockIdx.x * 256 + threadIdx.x;
    const float4* src;
    float4* dst;
    int j;
    if (i < N4_X)            { src = (const float4*)x;   dst = (float4*)xc;  j = i; }
    else if (i < N4_X + N4_W1) { src = (const float4*)w1i; dst = (float4*)w1o; j = i - N4_X; }
    else                     { src = (const float4*)w2i; dst = (float4*)w2o; j = i - N4_X - N4_W1; }
    float4 v = src[j];
    v.x = cvt_tf32_f(v.x); v.y = cvt_tf32_f(v.y);
    v.z = cvt_tf32_f(v.z); v.w = cvt_tf32_f(v.w);
    dst[j] = v;
}

// ---------------------------------------------------------------------------
// TF32 mma.sync GEMM (128x128 CTA, 64x32 warp tile, 8 warps, BK=32,
// 3-stage cp.async, 2 CTAs/SM). B fragments now via ldsm_x4 (2 bands/instr).
// Two epilogues: standard (out-proj) and fused QKV (bias+RoPE+scatter).
// ---------------------------------------------------------------------------
#define BKC 32
#define STAGE_BYTES 32768
#define GEMM_SMEM (3 * STAGE_BYTES)

__global__ void __launch_bounds__(256, 2) gemm_tf32(
    const float* __restrict__ A, const float* __restrict__ B,
    const float* __restrict__ bias, float* __restrict__ C,
    const float* __restrict__ ropeG,
    float* __restrict__ qo, float* __restrict__ ko, float* __restrict__ vo,
    int M, int N, int K)
{
    extern __shared__ char smem[];
    const uint32_t sb = smem_u32(smem);
    const int tid  = threadIdx.x;
    const int lane = tid & 31;
    const int wid  = tid >> 5;
    const int row0 = blockIdx.y * 128;
    const int col0 = blockIdx.x * 128;
    const int wm = (wid >> 2) * 64;
    const int wn = (wid & 3) * 32;

    const int r = tid >> 3;
    const int c = tid & 7;
    const float* aSrc = A + (size_t)(row0 + r) * K + c * 4;
    const float* bSrc = B + (size_t)(col0 + r) * K + c * 4;
    uint32_t dOff[4];
    #pragma unroll
    for (int l = 0; l < 4; l++) {
        int row = r + 32 * l;
        dOff[l] = (uint32_t)(row * 128 + ((c * 16) ^ ((row & 7) << 4)));
    }

    const int nk = K / BKC;

    uint32_t aRow[4], bRow4[2];
    #pragma unroll
    for (int mi = 0; mi < 4; mi++) aRow[mi] = (uint32_t)((wm + mi * 16 + (lane & 15)) * 128);
    // ldsm_x4 B addressing: lanes 0-7 rows n..n+7 seg0, 8-15 same rows seg1,
    // 16-23 rows n+8..n+15 seg0, 24-31 seg1  -> regs {band ni, band ni+1}
    #pragma unroll
    for (int pi = 0; pi < 2; pi++)
        bRow4[pi] = (uint32_t)((wn + pi * 16 + (lane & 7) + ((lane >> 4) << 3)) * 128);
    const uint32_t xorv = (uint32_t)((lane & 7) << 4);
    const uint32_t aseg = (uint32_t)((lane >> 4) * 16);
    const uint32_t bseg = (uint32_t)(((lane >> 3) & 1) * 16);

    float acc[16][4];
    #pragma unroll
    for (int t = 0; t < 16; t++)
        #pragma unroll
        for (int j = 0; j < 4; j++) acc[t][j] = 0.f;

    #pragma unroll
    for (int p = 0; p < 2; p++) {
        uint32_t base = sb + p * STAGE_BYTES;
        size_t koff = (size_t)p * BKC;
        #pragma unroll
        for (int l = 0; l < 4; l++) CP16(base + dOff[l],         aSrc + (size_t)l * 32 * K + koff);
        #pragma unroll
        for (int l = 0; l < 4; l++) CP16(base + 16384 + dOff[l], bSrc + (size_t)l * 32 * K + koff);
        CP_COMMIT();
    }

    int sCur = 0, sNext = 2;
    for (int i = 0; i < nk; i++) {
        CP_WAIT1();
        __syncthreads();

        if (i + 2 < nk) {
            uint32_t base = sb + sNext * STAGE_BYTES;
            size_t koff = (size_t)(i + 2) * BKC;
            #pragma unroll
            for (int l = 0; l < 4; l++) CP16(base + dOff[l],         aSrc + (size_t)l * 32 * K + koff);
            #pragma unroll
            for (int l = 0; l < 4; l++) CP16(base + 16384 + dOff[l], bSrc + (size_t)l * 32 * K + koff);
        }
        CP_COMMIT();

        const uint32_t aBase = sb + sCur * STAGE_BYTES;
        const uint32_t bBase = aBase + 16384;

        #pragma unroll
        for (int ks = 0; ks < 4; ks++) {
            const uint32_t kb = (uint32_t)(ks * 32);
            uint32_t af[4][4], bf[2][4];
            #pragma unroll
            for (int mi = 0; mi < 4; mi++)
                ldsm_x4(af[mi], aBase + aRow[mi] + ((kb + aseg) ^ xorv));
            #pragma unroll
            for (int pi = 0; pi < 2; pi++)
                ldsm_x4(bf[pi], bBase + bRow4[pi] + ((kb + bseg) ^ xorv));
            #pragma unroll
            for (int mi = 0; mi < 4; mi++)
                #pragma unroll
                for (int ni = 0; ni < 4; ni++)
                    mma_tf32(acc[mi * 4 + ni], af[mi], &bf[ni >> 1][(ni & 1) * 2]);
        }

        sCur = (sCur + 1) % 3;
        sNext = (sNext + 1) % 3;
    }

    const int gq = lane >> 2;
    const int qc = lane & 3;

    if (qo == nullptr) {
        #pragma unroll
        for (int mi = 0; mi < 4; mi++) {
            #pragma unroll
            for (int ni = 0; ni < 4; ni++) {
                const float* ac = acc[mi * 4 + ni];
                int colb = col0 + wn + ni * 8 + qc * 2;
                float b0 = __ldg(&bias[colb]);
                float b1 = __ldg(&bias[colb + 1]);
                size_t base0 = (size_t)(row0 + wm + mi * 16 + gq) * N + colb;
                C[base0]         = ac[0] + b0;
                C[base0 + 1]     = ac[1] + b1;
                C[base0 + 8 * (size_t)N]     = ac[2] + b0;
                C[base0 + 8 * (size_t)N + 1] = ac[3] + b1;
            }
        }
        return;
    }

    // ---- fused QKV epilogue: bias + RoPE + scatter to q/k/v [B,H,T,hd] ----
    const int colband = col0 + wn;
    const int region  = colband >> 11;      // 0=q 1=k 2=v
    const int cb      = colband & 2047;
    const int h       = cb >> 6;
    const int hb      = cb & 63;            // 0 (rope half) or 32 (pass half)
    float* dst = (region == 0) ? qo : (region == 1) ? ko : vo;

    #pragma unroll
    for (int mi = 0; mi < 4; mi++) {
        const int rr = row0 + wm + mi * 16 + gq;
        const int bb = rr >> 10;
        const int t  = rr & 1023;
        const size_t base0 = ((size_t)(bb * NHEAD + h) * SEQ + t) * HDIM;
        const size_t base1 = base0 + 8 * HDIM;

        if (region == 2 || hb == 32) {
            #pragma unroll
            for (int ni = 0; ni < 4; ni++) {
                const float* ac = acc[mi * 4 + ni];
                int dc = ni * 8 + qc * 2;
                int d  = hb + dc;
                float b0 = __ldg(&bias[colband + dc]);
                float b1 = __ldg(&bias[colband + dc + 1]);
                dst[base0 + d]     = cvt_tf32_f(ac[0] + b0);
                dst[base0 + d + 1] = cvt_tf32_f(ac[1] + b1);
                dst[base1 + d]     = cvt_tf32_f(ac[2] + b0);
                dst[base1 + d + 1] = cvt_tf32_f(ac[3] + b1);
            }
        } else {
            #pragma unroll
            for (int ni = 0; ni < 2; ni++) {
                const float* a1 = acc[mi * 4 + ni];
                const float* a2 = acc[mi * 4 + ni + 2];
                const int d = ni * 8 + qc * 2;
                float bl[2], bh2[2];
                bl[0]  = __ldg(&bias[colband + d]);
                bl[1]  = __ldg(&bias[colband + d + 1]);
                bh2[0] = __ldg(&bias[colband + d + 16]);
                bh2[1] = __ldg(&bias[colband + d + 17]);
                #pragma unroll
                for (int e = 0; e < 2; e++) {
                    const int j = d + e;
                    float2 cs0 = *reinterpret_cast<const float2*>(&ropeG[((size_t)t * 16 + j) * 2]);
                    float2 cs1 = *reinterpret_cast<const float2*>(&ropeG[((size_t)(t + 8) * 16 + j) * 2]);
                    float x1r0 = a1[e]     + bl[e];
                    float x2r0 = a2[e]     + bh2[e];
                    float x1r1 = a1[e + 2] + bl[e];
                    float x2r1 = a2[e + 2] + bh2[e];
                    dst[base0 + j]      = cvt_tf32_f(x1r0 * cs0.x - x2r0 * cs0.y);
                    dst[base0 + j + 16] = cvt_tf32_f(x2r0 * cs0.x + x1r0 * cs0.y);
                    dst[base1 + j]      = cvt_tf32_f(x1r1 * cs1.x - x2r1 * cs1.y);
                    dst[base1 + j + 16] = cvt_tf32_f(x2r1 * cs1.x + x1r1 * cs1.y);
                }
            }
        }
    }
}

// ---------------------------------------------------------------------------
// Tensor-core causal flash attention (tf32 mma.sync).
// B fragments via ldsm_x4; longest q-tiles launch first (reversed qt).
// ---------------------------------------------------------------------------
#define ATTN_SMEM2 98304
#define OFF_QS 0u
#define OFF_KS 32768u
#define OFF_VT 49152u
#define OFF_PS 65536u

__global__ void __launch_bounds__(256) attn_tc(
    const float* __restrict__ Q, const float* __restrict__ K,
    const float* __restrict__ V, float* __restrict__ ctx)
{
    extern __shared__ char smem[];
    const uint32_t sb = smem_u32(smem);
    const int tid  = threadIdx.x;
    const int lane = tid & 31;
    const int wid  = tid >> 5;
    const int bh   = blockIdx.y;
    const int b    = bh >> 5;
    const int h    = bh & 31;
    const int qt   = gridDim.x - 1 - blockIdx.x;   // long blocks first
    const int q0   = qt * 128;

    const float* Qg = Q + ((size_t)bh * SEQ + q0) * HDIM;
    #pragma unroll
    for (int l = 0; l < 8; l++) {
        int id  = tid + l * 256;
        int row = id >> 4;
        int d4  = id & 15;
        uint32_t dst = sb + OFF_QS + (uint32_t)((d4 >> 3) * 16384 + row * 128
                        + (((d4 & 7) * 16) ^ ((row & 7) << 4)));
        CP16(dst, Qg + row * HDIM + d4 * 4);
    }
    CP_COMMIT();

    const uint32_t aRow = (uint32_t)((wid * 16 + (lane & 15)) * 128);
    const uint32_t xorv = (uint32_t)((lane & 7) << 4);
    const uint32_t aseg = (uint32_t)((lane >> 4) * 16);
    const uint32_t bseg = (uint32_t)(((lane >> 3) & 1) * 16);
    // ldsm_x4 B addressing (2 bands per instr)
    uint32_t bRow4[4];
    #pragma unroll
    for (int pi = 0; pi < 4; pi++)
        bRow4[pi] = (uint32_t)((pi * 16 + (lane & 7) + ((lane >> 4) << 3)) * 128);
    const int gq = lane >> 2;
    const int qc = lane & 3;

    float o[8][4];
    #pragma unroll
    for (int ni = 0; ni < 8; ni++)
        #pragma unroll
        for (int e = 0; e < 4; e++) o[ni][e] = 0.f;
    float m0 = -1e30f, m1 = -1e30f, l0 = 0.f, l1 = 0.f;

    const int rowmin = q0 + wid * 16;
    const int rowmax = rowmin + 15;
    const int r0g = rowmin + gq;
    const int r1g = r0g + 8;
    const int nkt = 2 * qt + 2;
    const float scale = 0.125f;

    for (int kt = 0; kt < nkt; kt++) {
        const int k0 = kt * 64;
        __syncthreads();

        const float* Kg = K + ((size_t)bh * SEQ + k0) * HDIM;
        #pragma unroll
        for (int l = 0; l < 4; l++) {
            int id = tid + l * 256;
            int kk = id >> 4;
            int d4 = id & 15;
            uint32_t dst = sb + OFF_KS + (uint32_t)((d4 >> 3) * 8192 + kk * 128
                            + (((d4 & 7) * 16) ^ ((kk & 7) << 4)));
            CP16(dst, Kg + kk * HDIM + d4 * 4);
        }
        CP_COMMIT();

        const float* Vg = V + ((size_t)bh * SEQ + k0) * HDIM;
        #pragma unroll
        for (int l = 0; l < 4; l++) {
            int id = tid + l * 256;
            int kk = id >> 4;
            int d4 = id & 15;
            float4 vv = *reinterpret_cast<const float4*>(Vg + kk * HDIM + d4 * 4);
            #pragma unroll
            for (int i = 0; i < 4; i++) {
                int dd = d4 * 4 + i;
                uint32_t adr = sb + OFF_VT + (uint32_t)((kk >> 5) * 8192 + dd * 128
                                + (((kk & 31) * 4) ^ ((dd & 7) << 4)));
                float fv = (i == 0) ? vv.x : (i == 1) ? vv.y : (i == 2) ? vv.z : vv.w;
                asm volatile("st.shared.f32 [%0], %1;" :: "r"(adr), "f"(fv) : "memory");
            }
        }
        CP_WAIT0();
        __syncthreads();

        if (k0 <= rowmax) {
            float s[8][4];
            #pragma unroll
            for (int ni = 0; ni < 8; ni++)
                #pragma unroll
                for (int e = 0; e < 4; e++) s[ni][e] = 0.f;

            #pragma unroll
            for (int pn = 0; pn < 2; pn++) {
                const uint32_t qb = sb + OFF_QS + pn * 16384u;
                const uint32_t kb_ = sb + OFF_KS + pn * 8192u;
                #pragma unroll
                for (int k8 = 0; k8 < 4; k8++) {
                    const uint32_t kb = (uint32_t)(k8 * 32);
                    uint32_t af[4];
                    ldsm_x4(af, qb + aRow + ((kb + aseg) ^ xorv));
                    #pragma unroll
                    for (int pi = 0; pi < 4; pi++) {
                        uint32_t bq[4];
                        ldsm_x4(bq, kb_ + bRow4[pi] + ((kb + bseg) ^ xorv));
                        mma_tf32(s[pi * 2],     af, &bq[0]);
                        mma_tf32(s[pi * 2 + 1], af, &bq[2]);
                    }
                }
            }

            const bool need_mask = (k0 + 63 > rowmin);
            #pragma unroll
            for (int ni = 0; ni < 8; ni++) {
                int c0 = k0 + ni * 8 + qc * 2;
                if (need_mask) {
                    s[ni][0] = (c0     > r0g) ? -1e30f : s[ni][0] * scale;
                    s[ni][1] = (c0 + 1 > r0g) ? -1e30f : s[ni][1] * scale;
                    s[ni][2] = (c0     > r1g) ? -1e30f : s[ni][2] * scale;
                    s[ni][3] = (c0 + 1 > r1g) ? -1e30f : s[ni][3] * scale;
                } else {
                    s[ni][0] *= scale; s[ni][1] *= scale;
                    s[ni][2] *= scale; s[ni][3] *= scale;
                }
            }

            float mx0 = -1e30f, mx1 = -1e30f;
            #pragma unroll
            for (int ni = 0; ni < 8; ni++) {
                mx0 = fmaxf(mx0, fmaxf(s[ni][0], s[ni][1]));
                mx1 = fmaxf(mx1, fmaxf(s[ni][2], s[ni][3]));
            }
            mx0 = fmaxf(mx0, __shfl_xor_sync(0xffffffffu, mx0, 1));
            mx0 = fmaxf(mx0, __shfl_xor_sync(0xffffffffu, mx0, 2));
            mx1 = fmaxf(mx1, __shfl_xor_sync(0xffffffffu, mx1, 1));
            mx1 = fmaxf(mx1, __shfl_xor_sync(0xffffffffu, mx1, 2));

            const float mn0 = fmaxf(m0, mx0);
            const float mn1 = fmaxf(m1, mx1);
            const float corr0 = __expf(m0 - mn0);
            const float corr1 = __expf(m1 - mn1);

            float rs0 = 0.f, rs1 = 0.f;
            const int prow0 = wid * 16 + gq;
            #pragma unroll
            for (int ni = 0; ni < 8; ni++) {
                float p0 = __expf(s[ni][0] - mn0);
                float p1 = __expf(s[ni][1] - mn0);
                float p2 = __expf(s[ni][2] - mn1);
                float p3 = __expf(s[ni][3] - mn1);
                rs0 += p0 + p1;
                rs1 += p2 + p3;
                int col = ni * 8 + qc * 2;
                uint32_t pa = sb + OFF_PS + (uint32_t)((col >> 5) * 16384
                               + prow0 * 128 + (((col & 31) * 4) ^ ((gq & 7) << 4)));
                asm volatile("st.shared.v2.f32 [%0], {%1,%2};"
                    :: "r"(pa), "f"(cvt_tf32_f(p0)), "f"(cvt_tf32_f(p1)) : "memory");
                asm volatile("st.shared.v2.f32 [%0], {%1,%2};"
                    :: "r"(pa + 8 * 128), "f"(cvt_tf32_f(p2)), "f"(cvt_tf32_f(p3)) : "memory");
            }
            rs0 += __shfl_xor_sync(0xffffffffu, rs0, 1);
            rs0 += __shfl_xor_sync(0xffffffffu, rs0, 2);
            rs1 += __shfl_xor_sync(0xffffffffu, rs1, 1);
            rs1 += __shfl_xor_sync(0xffffffffu, rs1, 2);

            l0 = l0 * corr0 + rs0;
            l1 = l1 * corr1 + rs1;
            m0 = mn0; m1 = mn1;

            #pragma unroll
            for (int ni = 0; ni < 8; ni++) {
                o[ni][0] *= corr0; o[ni][1] *= corr0;
                o[ni][2] *= corr1; o[ni][3] *= corr1;
            }
            __syncwarp();

            #pragma unroll
            for (int pn = 0; pn < 2; pn++) {
                const uint32_t pb = sb + OFF_PS + pn * 16384u;
                const uint32_t vb = sb + OFF_VT + pn * 8192u;
                #pragma unroll
                for (int k8 = 0; k8 < 4; k8++) {
                    const uint32_t kb = (uint32_t)(k8 * 32);
                    uint32_t af[4];
                    ldsm_x4(af, pb + aRow + ((kb + aseg) ^ xorv));
                    #pragma unroll
                    for (int pi = 0; pi < 4; pi++) {
                        uint32_t bq[4];
                        ldsm_x4(bq, vb + bRow4[pi] + ((kb + bseg) ^ xorv));
                        mma_tf32(o[pi * 2],     af, &bq[0]);
                        mma_tf32(o[pi * 2 + 1], af, &bq[2]);
                    }
                }
            }
        }
    }

    const float inv0 = 1.f / l0;
    const float inv1 = 1.f / l1;
    const int t0 = q0 + wid * 16 + gq;
    float* c0p = ctx + ((size_t)b * SEQ + t0) * CDIM + h * HDIM;
    float* c1p = c0p + 8 * (size_t)CDIM;
    #pragma unroll
    for (int ni = 0; ni < 8; ni++) {
        int d = ni * 8 + qc * 2;
        float2 w0 = make_float2(cvt_tf32_f(o[ni][0] * inv0), cvt_tf32_f(o[ni][1] * inv0));
        float2 w1 = make_float2(cvt_tf32_f(o[ni][2] * inv1), cvt_tf32_f(o[ni][3] * inv1));
        *reinterpret_cast<float2*>(c0p + d) = w0;
        *reinterpret_cast<float2*>(c1p + d) = w1;
    }
}

// ---------------------------------------------------------------------------
extern "C" void kernel_launch(void* const* d_in, const int* in_sizes, int n_in,
                              void* d_out, int out_size)
{
    const float* x      = (const float*)d_in[0];
    const float* rope   = (const float*)d_in[3];
    const float* Wqkv_w = (const float*)d_in[4];
    const float* Wqkv_b = (const float*)d_in[5];
    const float* out_w  = (const float*)d_in[6];
    const float* out_b  = (const float*)d_in[7];
    float* out = (float*)d_out;

    float *ctx, *q, *k, *v, *xc, *w1, *w2;
    cudaGetSymbolAddress((void**)&ctx, g_ctx);
    cudaGetSymbolAddress((void**)&q,   g_q);
    cudaGetSymbolAddress((void**)&k,   g_k);
    cudaGetSymbolAddress((void**)&v,   g_v);
    cudaGetSymbolAddress((void**)&xc,  g_xc);
    cudaGetSymbolAddress((void**)&w1,  g_w1);
    cudaGetSymbolAddress((void**)&w2,  g_w2);

    cudaFuncSetAttribute(gemm_tf32, cudaFuncAttributeMaxDynamicSharedMemorySize, GEMM_SMEM);
    cudaFuncSetAttribute(gemm_tf32, cudaFuncAttributePreferredSharedMemoryCarveout, 100);
    cudaFuncSetAttribute(attn_tc, cudaFuncAttributeMaxDynamicSharedMemorySize, ATTN_SMEM2);
    cudaFuncSetAttribute(attn_tc, cudaFuncAttributePreferredSharedMemoryCarveout, 100);

    // 0) single merged tf32 pre-round pass
    cvt_tf32_all<<<(N4_X + N4_W1 + N4_W2) / 256, 256>>>(x, xc, Wqkv_w, w1, out_w, w2);

    // 1) QKV projection fused with bias + RoPE + q/k/v scatter
    gemm_tf32<<<dim3(QKVN / 128, MROWS / 128), 256, GEMM_SMEM>>>(
        xc, w1, Wqkv_b, nullptr, rope, q, k, v, MROWS, QKVN, CDIM);

    // 2) causal attention on tensor cores
    attn_tc<<<dim3(SEQ / 128, BATCH * NHEAD), 256, ATTN_SMEM2>>>(q, k, v, ctx);

    // 3) output projection (standard epilogue)
    gemm_tf32<<<dim3(CDIM / 128, MROWS / 128), 256, GEMM_SMEM>>>(
        ctx, w2, out_b, out, nullptr, nullptr, nullptr, nullptr, MROWS, CDIM, CDIM);
}

// round 12
// speedup vs baseline: 1.1789x; 1.0207x over previous
#include <cuda_runtime.h>
#include <cuda_bf16.h>
#include <cstdint>

// Problem constants
#define BATCH 4
#define SEQ   1024
#define CDIM  2048
#define NHEAD 32
#define HDIM  64
#define QKVN  (3*CDIM)          // 6144
#define MROWS (BATCH*SEQ)       // 4096

// Scratch (device globals: allocation-free rule)
__device__ float g_ctx[(size_t)MROWS * CDIM];
__device__ float g_q[(size_t)BATCH*NHEAD*SEQ*HDIM];
__device__ float g_k[(size_t)BATCH*NHEAD*SEQ*HDIM];
__device__ float g_v[(size_t)BATCH*NHEAD*SEQ*HDIM];
// tf32-pre-rounded operand copies
__device__ float g_xc[(size_t)MROWS * CDIM];
__device__ float g_w1[(size_t)QKVN * CDIM];
__device__ float g_w2[(size_t)CDIM * CDIM];

// ---------------------------------------------------------------------------
// helpers
// ---------------------------------------------------------------------------
__device__ __forceinline__ uint32_t smem_u32(const void* p) {
    uint32_t a;
    asm("{ .reg .u64 t; cvta.to.shared.u64 t, %1; cvt.u32.u64 %0, t; }" : "=r"(a) : "l"(p));
    return a;
}
#define CP16(dst, src) \
    asm volatile("cp.async.cg.shared.global [%0], [%1], 16;" :: "r"(dst), "l"(src) : "memory")
#define CP_COMMIT() asm volatile("cp.async.commit_group;" ::: "memory")
#define CP_WAIT1()  asm volatile("cp.async.wait_group 1;" ::: "memory")
#define CP_WAIT0()  asm volatile("cp.async.wait_group 0;" ::: "memory")

__device__ __forceinline__ void ldsm_x4(uint32_t a[4], uint32_t addr) {
    asm volatile("ldmatrix.sync.aligned.m8n8.x4.shared.b16 {%0,%1,%2,%3}, [%4];"
        : "=r"(a[0]), "=r"(a[1]), "=r"(a[2]), "=r"(a[3]) : "r"(addr));
}
__device__ __forceinline__ float cvt_tf32_f(float x) {
    uint32_t r;
    asm("cvt.rna.tf32.f32 %0, %1;" : "=r"(r) : "f"(x));
    return __uint_as_float(r);
}
__device__ __forceinline__ void mma_tf32(float c[4], const uint32_t a[4], const uint32_t b[2]) {
    asm volatile(
        "mma.sync.aligned.m16n8k8.row.col.f32.tf32.tf32.f32 "
        "{%0,%1,%2,%3}, {%4,%5,%6,%7}, {%8,%9}, {%0,%1,%2,%3};"
        : "+f"(c[0]), "+f"(c[1]), "+f"(c[2]), "+f"(c[3])
        : "r"(a[0]), "r"(a[1]), "r"(a[2]), "r"(a[3]), "r"(b[0]), "r"(b[1]));
}

// ---------------------------------------------------------------------------
// merged tf32 pre-round pass over x, Wqkv_w, out_w (single launch)
// ---------------------------------------------------------------------------
#define N4_X  (MROWS * CDIM / 4)
#define N4_W1 (QKVN * CDIM / 4)
#define N4_W2 (CDIM * CDIM / 4)

__global__ void __launch_bounds__(256) cvt_tf32_all(
    const float* __restrict__ x,  float* __restrict__ xc,
    const float* __restrict__ w1i, float* __restrict__ w1o,
    const float* __restrict__ w2i, float* __restrict__ w2o)
{
    int i = blockIdx.x * 256 + threadIdx.x;
    const float4* src;
    float4* dst;
    int j;
    if (i < N4_X)            { src = (const float4*)x;   dst = (float4*)xc;  j = i; }
    else if (i < N4_X + N4_W1) { src = (const float4*)w1i; dst = (float4*)w1o; j = i - N4_X; }
    else                     { src = (const float4*)w2i; dst = (float4*)w2o; j = i - N4_X - N4_W1; }
    float4 v = src[j];
    v.x = cvt_tf32_f(v.x); v.y = cvt_tf32_f(v.y);
    v.z = cvt_tf32_f(v.z); v.w = cvt_tf32_f(v.w);
    dst[j] = v;
}

// ---------------------------------------------------------------------------
// TF32 mma.sync GEMM (128x128 CTA, 64x32 warp tile, 8 warps, BK=32,
// 3-stage cp.async, 2 CTAs/SM). Persistent grid-stride tile loop to kill
// wave quantization (fold the partial last wave into the first CTAs).
// Two epilogues: standard (out-proj) and fused QKV (bias+RoPE+scatter).
// ---------------------------------------------------------------------------
#define BKC 32
#define STAGE_BYTES 32768
#define GEMM_SMEM (3 * STAGE_BYTES)
#define QKV_GRID 1480    // 5 exact waves on 148 SMs x 2 CTAs; 56 CTAs fold 2 tiles

__global__ void __launch_bounds__(256, 2) gemm_tf32(
    const float* __restrict__ A, const float* __restrict__ B,
    const float* __restrict__ bias, float* __restrict__ C,
    const float* __restrict__ ropeG,
    float* __restrict__ qo, float* __restrict__ ko, float* __restrict__ vo,
    int M, int N, int K, int tilesX, int tilesTot)
{
    extern __shared__ char smem[];
    const uint32_t sb = smem_u32(smem);
    const int tid  = threadIdx.x;
    const int lane = tid & 31;
    const int wid  = tid >> 5;
    const int wm = (wid >> 2) * 64;
    const int wn = (wid & 3) * 32;

    const int r = tid >> 3;
    const int c = tid & 7;
    uint32_t dOff[4];
    #pragma unroll
    for (int l = 0; l < 4; l++) {
        int row = r + 32 * l;
        dOff[l] = (uint32_t)(row * 128 + ((c * 16) ^ ((row & 7) << 4)));
    }

    const int nk = K / BKC;

    uint32_t aRow[4], bRow4[2];
    #pragma unroll
    for (int mi = 0; mi < 4; mi++) aRow[mi] = (uint32_t)((wm + mi * 16 + (lane & 15)) * 128);
    #pragma unroll
    for (int pi = 0; pi < 2; pi++)
        bRow4[pi] = (uint32_t)((wn + pi * 16 + (lane & 7) + ((lane >> 4) << 3)) * 128);
    const uint32_t xorv = (uint32_t)((lane & 7) << 4);
    const uint32_t aseg = (uint32_t)((lane >> 4) * 16);
    const uint32_t bseg = (uint32_t)(((lane >> 3) & 1) * 16);
    const int gq = lane >> 2;
    const int qc = lane & 3;

    for (int tidx = blockIdx.x; tidx < tilesTot; tidx += gridDim.x) {
        const int row0 = (tidx / tilesX) * 128;
        const int col0 = (tidx % tilesX) * 128;
        const float* aSrc = A + (size_t)(row0 + r) * K + c * 4;
        const float* bSrc = B + (size_t)(col0 + r) * K + c * 4;

        __syncthreads();   // protect stages from previous tile's readers

        float acc[16][4];
        #pragma unroll
        for (int t = 0; t < 16; t++)
            #pragma unroll
            for (int j = 0; j < 4; j++) acc[t][j] = 0.f;

        #pragma unroll
        for (int p = 0; p < 2; p++) {
            uint32_t base = sb + p * STAGE_BYTES;
            size_t koff = (size_t)p * BKC;
            #pragma unroll
            for (int l = 0; l < 4; l++) CP16(base + dOff[l],         aSrc + (size_t)l * 32 * K + koff);
            #pragma unroll
            for (int l = 0; l < 4; l++) CP16(base + 16384 + dOff[l], bSrc + (size_t)l * 32 * K + koff);
            CP_COMMIT();
        }

        int sCur = 0, sNext = 2;
        for (int i = 0; i < nk; i++) {
            CP_WAIT1();
            __syncthreads();

            if (i + 2 < nk) {
                uint32_t base = sb + sNext * STAGE_BYTES;
                size_t koff = (size_t)(i + 2) * BKC;
                #pragma unroll
                for (int l = 0; l < 4; l++) CP16(base + dOff[l],         aSrc + (size_t)l * 32 * K + koff);
                #pragma unroll
                for (int l = 0; l < 4; l++) CP16(base + 16384 + dOff[l], bSrc + (size_t)l * 32 * K + koff);
            }
            CP_COMMIT();

            const uint32_t aBase = sb + sCur * STAGE_BYTES;
            const uint32_t bBase = aBase + 16384;

            #pragma unroll
            for (int ks = 0; ks < 4; ks++) {
                const uint32_t kb = (uint32_t)(ks * 32);
                uint32_t af[4][4], bf[2][4];
                #pragma unroll
                for (int mi = 0; mi < 4; mi++)
                    ldsm_x4(af[mi], aBase + aRow[mi] + ((kb + aseg) ^ xorv));
                #pragma unroll
                for (int pi = 0; pi < 2; pi++)
                    ldsm_x4(bf[pi], bBase + bRow4[pi] + ((kb + bseg) ^ xorv));
                #pragma unroll
                for (int mi = 0; mi < 4; mi++)
                    #pragma unroll
                    for (int ni = 0; ni < 4; ni++)
                        mma_tf32(acc[mi * 4 + ni], af[mi], &bf[ni >> 1][(ni & 1) * 2]);
            }

            sCur = (sCur + 1) % 3;
            sNext = (sNext + 1) % 3;
        }

        if (qo == nullptr) {
            #pragma unroll
            for (int mi = 0; mi < 4; mi++) {
                #pragma unroll
                for (int ni = 0; ni < 4; ni++) {
                    const float* ac = acc[mi * 4 + ni];
                    int colb = col0 + wn + ni * 8 + qc * 2;
                    float b0 = __ldg(&bias[colb]);
                    float b1 = __ldg(&bias[colb + 1]);
                    size_t base0 = (size_t)(row0 + wm + mi * 16 + gq) * N + colb;
                    C[base0]         = ac[0] + b0;
                    C[base0 + 1]     = ac[1] + b1;
                    C[base0 + 8 * (size_t)N]     = ac[2] + b0;
                    C[base0 + 8 * (size_t)N + 1] = ac[3] + b1;
                }
            }
            continue;
        }

        // ---- fused QKV epilogue: bias + RoPE + scatter to q/k/v [B,H,T,hd] ----
        const int colband = col0 + wn;
        const int region  = colband >> 11;      // 0=q 1=k 2=v
        const int cb      = colband & 2047;
        const int h       = cb >> 6;
        const int hb      = cb & 63;            // 0 (rope half) or 32 (pass half)
        float* dst = (region == 0) ? qo : (region == 1) ? ko : vo;

        #pragma unroll
        for (int mi = 0; mi < 4; mi++) {
            const int rr = row0 + wm + mi * 16 + gq;
            const int bb = rr >> 10;
            const int t  = rr & 1023;
            const size_t base0 = ((size_t)(bb * NHEAD + h) * SEQ + t) * HDIM;
            const size_t base1 = base0 + 8 * HDIM;

            if (region == 2 || hb == 32) {
                #pragma unroll
                for (int ni = 0; ni < 4; ni++) {
                    const float* ac = acc[mi * 4 + ni];
                    int dc = ni * 8 + qc * 2;
                    int d  = hb + dc;
                    float b0 = __ldg(&bias[colband + dc]);
                    float b1 = __ldg(&bias[colband + dc + 1]);
                    dst[base0 + d]     = cvt_tf32_f(ac[0] + b0);
                    dst[base0 + d + 1] = cvt_tf32_f(ac[1] + b1);
                    dst[base1 + d]     = cvt_tf32_f(ac[2] + b0);
                    dst[base1 + d + 1] = cvt_tf32_f(ac[3] + b1);
                }
            } else {
                #pragma unroll
                for (int ni = 0; ni < 2; ni++) {
                    const float* a1 = acc[mi * 4 + ni];
                    const float* a2 = acc[mi * 4 + ni + 2];
                    const int d = ni * 8 + qc * 2;
                    float bl[2], bh2[2];
                    bl[0]  = __ldg(&bias[colband + d]);
                    bl[1]  = __ldg(&bias[colband + d + 1]);
                    bh2[0] = __ldg(&bias[colband + d + 16]);
                    bh2[1] = __ldg(&bias[colband + d + 17]);
                    #pragma unroll
                    for (int e = 0; e < 2; e++) {
                        const int j = d + e;
                        float2 cs0 = *reinterpret_cast<const float2*>(&ropeG[((size_t)t * 16 + j) * 2]);
                        float2 cs1 = *reinterpret_cast<const float2*>(&ropeG[((size_t)(t + 8) * 16 + j) * 2]);
                        float x1r0 = a1[e]     + bl[e];
                        float x2r0 = a2[e]     + bh2[e];
                        float x1r1 = a1[e + 2] + bl[e];
                        float x2r1 = a2[e + 2] + bh2[e];
                        dst[base0 + j]      = cvt_tf32_f(x1r0 * cs0.x - x2r0 * cs0.y);
                        dst[base0 + j + 16] = cvt_tf32_f(x2r0 * cs0.x + x1r0 * cs0.y);
                        dst[base1 + j]      = cvt_tf32_f(x1r1 * cs1.x - x2r1 * cs1.y);
                        dst[base1 + j + 16] = cvt_tf32_f(x2r1 * cs1.x + x1r1 * cs1.y);
                    }
                }
            }
        }
    }
}

// ---------------------------------------------------------------------------
// Tensor-core causal flash attention (tf32 mma.sync). Unchanged from R11.
// ---------------------------------------------------------------------------
#define ATTN_SMEM2 98304
#define OFF_QS 0u
#define OFF_KS 32768u
#define OFF_VT 49152u
#define OFF_PS 65536u

__global__ void __launch_bounds__(256) attn_tc(
    const float* __restrict__ Q, const float* __restrict__ K,
    const float* __restrict__ V, float* __restrict__ ctx)
{
    extern __shared__ char smem[];
    const uint32_t sb = smem_u32(smem);
    const int tid  = threadIdx.x;
    const int lane = tid & 31;
    const int wid  = tid >> 5;
    const int bh   = blockIdx.y;
    const int b    = bh >> 5;
    const int h    = bh & 31;
    const int qt   = gridDim.x - 1 - blockIdx.x;   // long blocks first
    const int q0   = qt * 128;

    const float* Qg = Q + ((size_t)bh * SEQ + q0) * HDIM;
    #pragma unroll
    for (int l = 0; l < 8; l++) {
        int id  = tid + l * 256;
        int row = id >> 4;
        int d4  = id & 15;
        uint32_t dst = sb + OFF_QS + (uint32_t)((d4 >> 3) * 16384 + row * 128
                        + (((d4 & 7) * 16) ^ ((row & 7) << 4)));
        CP16(dst, Qg + row * HDIM + d4 * 4);
    }
    CP_COMMIT();

    const uint32_t aRow = (uint32_t)((wid * 16 + (lane & 15)) * 128);
    const uint32_t xorv = (uint32_t)((lane & 7) << 4);
    const uint32_t aseg = (uint32_t)((lane >> 4) * 16);
    const uint32_t bseg = (uint32_t)(((lane >> 3) & 1) * 16);
    uint32_t bRow4[4];
    #pragma unroll
    for (int pi = 0; pi < 4; pi++)
        bRow4[pi] = (uint32_t)((pi * 16 + (lane & 7) + ((lane >> 4) << 3)) * 128);
    const int gq = lane >> 2;
    const int qc = lane & 3;

    float o[8][4];
    #pragma unroll
    for (int ni = 0; ni < 8; ni++)
        #pragma unroll
        for (int e = 0; e < 4; e++) o[ni][e] = 0.f;
    float m0 = -1e30f, m1 = -1e30f, l0 = 0.f, l1 = 0.f;

    const int rowmin = q0 + wid * 16;
    const int rowmax = rowmin + 15;
    const int r0g = rowmin + gq;
    const int r1g = r0g + 8;
    const int nkt = 2 * qt + 2;
    const float scale = 0.125f;

    for (int kt = 0; kt < nkt; kt++) {
        const int k0 = kt * 64;
        __syncthreads();

        const float* Kg = K + ((size_t)bh * SEQ + k0) * HDIM;
        #pragma unroll
        for (int l = 0; l < 4; l++) {
            int id = tid + l * 256;
            int kk = id >> 4;
            int d4 = id & 15;
            uint32_t dst = sb + OFF_KS + (uint32_t)((d4 >> 3) * 8192 + kk * 128
                            + (((d4 & 7) * 16) ^ ((kk & 7) << 4)));
            CP16(dst, Kg + kk * HDIM + d4 * 4);
        }
        CP_COMMIT();

        const float* Vg = V + ((size_t)bh * SEQ + k0) * HDIM;
        #pragma unroll
        for (int l = 0; l < 4; l++) {
            int id = tid + l * 256;
            int kk = id >> 4;
            int d4 = id & 15;
            float4 vv = *reinterpret_cast<const float4*>(Vg + kk * HDIM + d4 * 4);
            #pragma unroll
            for (int i = 0; i < 4; i++) {
                int dd = d4 * 4 + i;
                uint32_t adr = sb + OFF_VT + (uint32_t)((kk >> 5) * 8192 + dd * 128
                                + (((kk & 31) * 4) ^ ((dd & 7) << 4)));
                float fv = (i == 0) ? vv.x : (i == 1) ? vv.y : (i == 2) ? vv.z : vv.w;
                asm volatile("st.shared.f32 [%0], %1;" :: "r"(adr), "f"(fv) : "memory");
            }
        }
        CP_WAIT0();
        __syncthreads();

        if (k0 <= rowmax) {
            float s[8][4];
            #pragma unroll
            for (int ni = 0; ni < 8; ni++)
                #pragma unroll
                for (int e = 0; e < 4; e++) s[ni][e] = 0.f;

            #pragma unroll
            for (int pn = 0; pn < 2; pn++) {
                const uint32_t qb = sb + OFF_QS + pn * 16384u;
                const uint32_t kb_ = sb + OFF_KS + pn * 8192u;
                #pragma unroll
                for (int k8 = 0; k8 < 4; k8++) {
                    const uint32_t kb = (uint32_t)(k8 * 32);
                    uint32_t af[4];
                    ldsm_x4(af, qb + aRow + ((kb + aseg) ^ xorv));
                    #pragma unroll
                    for (int pi = 0; pi < 4; pi++) {
                        uint32_t bq[4];
                        ldsm_x4(bq, kb_ + bRow4[pi] + ((kb + bseg) ^ xorv));
                        mma_tf32(s[pi * 2],     af, &bq[0]);
                        mma_tf32(s[pi * 2 + 1], af, &bq[2]);
                    }
                }
            }

            const bool need_mask = (k0 + 63 > rowmin);
            #pragma unroll
            for (int ni = 0; ni < 8; ni++) {
                int c0 = k0 + ni * 8 + qc * 2;
                if (need_mask) {
                    s[ni][0] = (c0     > r0g) ? -1e30f : s[ni][0] * scale;
                    s[ni][1] = (c0 + 1 > r0g) ? -1e30f : s[ni][1] * scale;
                    s[ni][2] = (c0     > r1g) ? -1e30f : s[ni][2] * scale;
                    s[ni][3] = (c0 + 1 > r1g) ? -1e30f : s[ni][3] * scale;
                } else {
                    s[ni][0] *= scale; s[ni][1] *= scale;
                    s[ni][2] *= scale; s[ni][3] *= scale;
                }
            }

            float mx0 = -1e30f, mx1 = -1e30f;
            #pragma unroll
            for (int ni = 0; ni < 8; ni++) {
                mx0 = fmaxf(mx0, fmaxf(s[ni][0], s[ni][1]));
                mx1 = fmaxf(mx1, fmaxf(s[ni][2], s[ni][3]));
            }
            mx0 = fmaxf(mx0, __shfl_xor_sync(0xffffffffu, mx0, 1));
            mx0 = fmaxf(mx0, __shfl_xor_sync(0xffffffffu, mx0, 2));
            mx1 = fmaxf(mx1, __shfl_xor_sync(0xffffffffu, mx1, 1));
            mx1 = fmaxf(mx1, __shfl_xor_sync(0xffffffffu, mx1, 2));

            const float mn0 = fmaxf(m0, mx0);
            const float mn1 = fmaxf(m1, mx1);
            const float corr0 = __expf(m0 - mn0);
            const float corr1 = __expf(m1 - mn1);

            float rs0 = 0.f, rs1 = 0.f;
            const int prow0 = wid * 16 + gq;
            #pragma unroll
            for (int ni = 0; ni < 8; ni++) {
                float p0 = __expf(s[ni][0] - mn0);
                float p1 = __expf(s[ni][1] - mn0);
                float p2 = __expf(s[ni][2] - mn1);
                float p3 = __expf(s[ni][3] - mn1);
                rs0 += p0 + p1;
                rs1 += p2 + p3;
                int col = ni * 8 + qc * 2;
                uint32_t pa = sb + OFF_PS + (uint32_t)((col >> 5) * 16384
                               + prow0 * 128 + (((col & 31) * 4) ^ ((gq & 7) << 4)));
                asm volatile("st.shared.v2.f32 [%0], {%1,%2};"
                    :: "r"(pa), "f"(cvt_tf32_f(p0)), "f"(cvt_tf32_f(p1)) : "memory");
                asm volatile("st.shared.v2.f32 [%0], {%1,%2};"
                    :: "r"(pa + 8 * 128), "f"(cvt_tf32_f(p2)), "f"(cvt_tf32_f(p3)) : "memory");
            }
            rs0 += __shfl_xor_sync(0xffffffffu, rs0, 1);
            rs0 += __shfl_xor_sync(0xffffffffu, rs0, 2);
            rs1 += __shfl_xor_sync(0xffffffffu, rs1, 1);
            rs1 += __shfl_xor_sync(0xffffffffu, rs1, 2);

            l0 = l0 * corr0 + rs0;
            l1 = l1 * corr1 + rs1;
            m0 = mn0; m1 = mn1;

            #pragma unroll
            for (int ni = 0; ni < 8; ni++) {
                o[ni][0] *= corr0; o[ni][1] *= corr0;
                o[ni][2] *= corr1; o[ni][3] *= corr1;
            }
            __syncwarp();

            #pragma unroll
            for (int pn = 0; pn < 2; pn++) {
                const uint32_t pb = sb + OFF_PS + pn * 16384u;
                const uint32_t vb = sb + OFF_VT + pn * 8192u;
                #pragma unroll
                for (int k8 = 0; k8 < 4; k8++) {
                    const uint32_t kb = (uint32_t)(k8 * 32);
                    uint32_t af[4];
                    ldsm_x4(af, pb + aRow + ((kb + aseg) ^ xorv));
                    #pragma unroll
                    for (int pi = 0; pi < 4; pi++) {
                        uint32_t bq[4];
                        ldsm_x4(bq, vb + bRow4[pi] + ((kb + bseg) ^ xorv));
                        mma_tf32(o[pi * 2],     af, &bq[0]);
                        mma_tf32(o[pi * 2 + 1], af, &bq[2]);
                    }
                }
            }
        }
    }

    const float inv0 = 1.f / l0;
    const float inv1 = 1.f / l1;
    const int t0 = q0 + wid * 16 + gq;
    float* c0p = ctx + ((size_t)b * SEQ + t0) * CDIM + h * HDIM;
    float* c1p = c0p + 8 * (size_t)CDIM;
    #pragma unroll
    for (int ni = 0; ni < 8; ni++) {
        int d = ni * 8 + qc * 2;
        float2 w0 = make_float2(cvt_tf32_f(o[ni][0] * inv0), cvt_tf32_f(o[ni][1] * inv0));
        float2 w1 = make_float2(cvt_tf32_f(o[ni][2] * inv1), cvt_tf32_f(o[ni][3] * inv1));
        *reinterpret_cast<float2*>(c0p + d) = w0;
        *reinterpret_cast<float2*>(c1p + d) = w1;
    }
}

// ---------------------------------------------------------------------------
extern "C" void kernel_launch(void* const* d_in, const int* in_sizes, int n_in,
                              void* d_out, int out_size)
{
    const float* x      = (const float*)d_in[0];
    const float* rope   = (const float*)d_in[3];
    const float* Wqkv_w = (const float*)d_in[4];
    const float* Wqkv_b = (const float*)d_in[5];
    const float* out_w  = (const float*)d_in[6];
    const float* out_b  = (const float*)d_in[7];
    float* out = (float*)d_out;

    float *ctx, *q, *k, *v, *xc, *w1, *w2;
    cudaGetSymbolAddress((void**)&ctx, g_ctx);
    cudaGetSymbolAddress((void**)&q,   g_q);
    cudaGetSymbolAddress((void**)&k,   g_k);
    cudaGetSymbolAddress((void**)&v,   g_v);
    cudaGetSymbolAddress((void**)&xc,  g_xc);
    cudaGetSymbolAddress((void**)&w1,  g_w1);
    cudaGetSymbolAddress((void**)&w2,  g_w2);

    cudaFuncSetAttribute(gemm_tf32, cudaFuncAttributeMaxDynamicSharedMemorySize, GEMM_SMEM);
    cudaFuncSetAttribute(gemm_tf32, cudaFuncAttributePreferredSharedMemoryCarveout, 100);
    cudaFuncSetAttribute(attn_tc, cudaFuncAttributeMaxDynamicSharedMemorySize, ATTN_SMEM2);
    cudaFuncSetAttribute(attn_tc, cudaFuncAttributePreferredSharedMemoryCarveout, 100);

    // 0) single merged tf32 pre-round pass
    cvt_tf32_all<<<(N4_X + N4_W1 + N4_W2) / 256, 256>>>(x, xc, Wqkv_w, w1, out_w, w2);

    // 1) QKV projection fused with bias + RoPE + q/k/v scatter.
    //    Folded grid: 1480 CTAs (5 exact waves), 56 CTAs run 2 tiles.
    gemm_tf32<<<QKV_GRID, 256, GEMM_SMEM>>>(
        xc, w1, Wqkv_b, nullptr, rope, q, k, v,
        MROWS, QKVN, CDIM, QKVN / 128, (QKVN / 128) * (MROWS / 128));

    // 2) causal attention on tensor cores
    attn_tc<<<dim3(SEQ / 128, BATCH * NHEAD), 256, ATTN_SMEM2>>>(q, k, v, ctx);

    // 3) output projection (standard epilogue; 512 tiles, 1 tile/CTA)
    gemm_tf32<<<512, 256, GEMM_SMEM>>>(
        ctx, w2, out_b, out, nullptr, nullptr, nullptr, nullptr,
        MROWS, CDIM, CDIM, CDIM / 128, (CDIM / 128) * (MROWS / 128));
}